// round 1
// baseline (speedup 1.0000x reference)
#include <cuda_runtime.h>
#include <math.h>

// ---------------------------------------------------------------------------
// Neural Cellular Automata step, fp32 baseline (two-pass).
//   Pass A: perceive (identity + sobel_x + sobel_y) -> MLP(48->128 relu ->16)
//           -> x_new = x + dx * (rand<=0.5); writes x_new + alpha planes.
//   Pass B: life = (maxpool3x3(alpha_old)>0.1) & (maxpool3x3(alpha_new)>0.1);
//           out = x_new * life.
// ---------------------------------------------------------------------------

#define CH    16
#define NK    48
#define HID   128
#define IMG   256
#define BATCH 16

// Scratch (allocation-free: __device__ globals)
__device__ float g_xnew[(size_t)BATCH * IMG * IMG * CH]; // 64 MB
__device__ float g_an[(size_t)BATCH * IMG * IMG];        // alpha of x_new
__device__ float g_ao[(size_t)BATCH * IMG * IMG];        // alpha of x

// ------------------------------- Pass A ------------------------------------
#define TA_H 4
#define TA_W 32
#define HA_H (TA_H + 2)
#define HA_W (TA_W + 2)
#define TA_THREADS (TA_H * TA_W)   // 128

__global__ __launch_bounds__(TA_THREADS, 2)
void nca_pass_a(const float* __restrict__ x,
                const float* __restrict__ w0,
                const float* __restrict__ w1,
                const float* __restrict__ rmask)
{
    // channel-planar x tile (conflict-free stencil loads) + weights
    __shared__ float sx[CH][HA_H * HA_W];      // 13056 B
    __shared__ float sw0[HID * NK];            // 24576 B  (row-major [hid][48])
    __shared__ float sw1t[HID * CH];           // 8192 B   (transposed [hid][16])

    const int tid = threadIdx.x;

    // Load weights (L2-resident across all 8192 blocks)
    for (int i = tid; i < HID * NK; i += TA_THREADS) sw0[i] = w0[i];
    for (int i = tid; i < HID * CH; i += TA_THREADS) {
        int c = i >> 4, o = i & 15;
        sw1t[i] = w1[o * HID + c];
    }

    // Block -> (b, ty0, tx0)
    int bb = blockIdx.x;
    const int tx0 = (bb % (IMG / TA_W)) * TA_W;  bb /= (IMG / TA_W);
    const int ty0 = (bb % (IMG / TA_H)) * TA_H;  bb /= (IMG / TA_H);
    const int b = bb;
    const float* ximg = x + (size_t)b * IMG * IMG * CH;

    // Load halo tile (zero padding = SAME conv)
    for (int p = tid; p < HA_H * HA_W; p += TA_THREADS) {
        const int hy = ty0 + (p / HA_W) - 1;
        const int hx = tx0 + (p % HA_W) - 1;
        if ((unsigned)hy < IMG && (unsigned)hx < IMG) {
            const float4* src = (const float4*)(ximg + ((size_t)hy * IMG + hx) * CH);
            #pragma unroll
            for (int q = 0; q < 4; q++) {
                float4 v = src[q];
                sx[4*q + 0][p] = v.x;
                sx[4*q + 1][p] = v.y;
                sx[4*q + 2][p] = v.z;
                sx[4*q + 3][p] = v.w;
            }
        } else {
            #pragma unroll
            for (int c = 0; c < CH; c++) sx[c][p] = 0.0f;
        }
    }
    __syncthreads();

    const int ty = tid / TA_W, tx = tid % TA_W;
    const int pc = (ty + 1) * HA_W + (tx + 1);

    // Perceive: y[3c]=x_c, y[3c+1]=sobel_x, y[3c+2]=sobel_y
    float y[NK];
    #pragma unroll
    for (int c = 0; c < CH; c++) {
        const float nw = sx[c][pc - HA_W - 1];
        const float nn = sx[c][pc - HA_W];
        const float ne = sx[c][pc - HA_W + 1];
        const float ww = sx[c][pc - 1];
        const float cc = sx[c][pc];
        const float ee = sx[c][pc + 1];
        const float sw = sx[c][pc + HA_W - 1];
        const float ss = sx[c][pc + HA_W];
        const float se = sx[c][pc + HA_W + 1];
        y[3*c + 0] = cc;
        y[3*c + 1] = ((ne + se) - (nw + sw) + 2.0f * (ee - ww)) * 0.125f;
        y[3*c + 2] = ((sw + se) - (nw + ne) + 2.0f * (ss - nn)) * 0.125f;
    }

    float dx[CH];
    #pragma unroll
    for (int o = 0; o < CH; o++) dx[o] = 0.0f;

    // MLP: dx += relu(w0[c,:] . y) * w1t[c,:]
    #pragma unroll 2
    for (int c = 0; c < HID; c++) {
        const float4* wr = (const float4*)(sw0 + c * NK);
        float a0 = 0.f, a1 = 0.f, a2 = 0.f, a3 = 0.f;
        #pragma unroll
        for (int j = 0; j < 3; j++) {   // 3 groups of 16 features
            const float4 v0 = wr[4*j + 0];
            const float4 v1 = wr[4*j + 1];
            const float4 v2 = wr[4*j + 2];
            const float4 v3 = wr[4*j + 3];
            a0 += v0.x * y[16*j + 0]  + v0.y * y[16*j + 1]  + v0.z * y[16*j + 2]  + v0.w * y[16*j + 3];
            a1 += v1.x * y[16*j + 4]  + v1.y * y[16*j + 5]  + v1.z * y[16*j + 6]  + v1.w * y[16*j + 7];
            a2 += v2.x * y[16*j + 8]  + v2.y * y[16*j + 9]  + v2.z * y[16*j + 10] + v2.w * y[16*j + 11];
            a3 += v3.x * y[16*j + 12] + v3.y * y[16*j + 13] + v3.z * y[16*j + 14] + v3.w * y[16*j + 15];
        }
        const float h = fmaxf((a0 + a1) + (a2 + a3), 0.0f);

        const float4* u = (const float4*)(sw1t + c * CH);
        const float4 u0 = u[0], u1 = u[1], u2 = u[2], u3 = u[3];
        dx[0]  += h * u0.x;  dx[1]  += h * u0.y;  dx[2]  += h * u0.z;  dx[3]  += h * u0.w;
        dx[4]  += h * u1.x;  dx[5]  += h * u1.y;  dx[6]  += h * u1.z;  dx[7]  += h * u1.w;
        dx[8]  += h * u2.x;  dx[9]  += h * u2.y;  dx[10] += h * u2.z;  dx[11] += h * u2.w;
        dx[12] += h * u3.x;  dx[13] += h * u3.y;  dx[14] += h * u3.z;  dx[15] += h * u3.w;
    }

    // Epilogue: x_new = x + dx * (rand <= 0.5)
    const int gy = ty0 + ty, gxp = tx0 + tx;
    const size_t pix = ((size_t)b * IMG + gy) * IMG + gxp;
    const float upd = (rmask[pix] <= 0.5f) ? 1.0f : 0.0f;

    float4* dst = (float4*)(g_xnew + pix * CH);
    float alpha_new = 0.0f;
    #pragma unroll
    for (int q = 0; q < 4; q++) {
        float4 v;
        v.x = sx[4*q + 0][pc] + dx[4*q + 0] * upd;
        v.y = sx[4*q + 1][pc] + dx[4*q + 1] * upd;
        v.z = sx[4*q + 2][pc] + dx[4*q + 2] * upd;
        v.w = sx[4*q + 3][pc] + dx[4*q + 3] * upd;
        dst[q] = v;
        if (q == 0) alpha_new = v.w;   // channel 3
    }
    g_an[pix] = alpha_new;
    g_ao[pix] = sx[3][pc];
}

// ------------------------------- Pass B ------------------------------------
#define TB_H 8
#define TB_W 32
#define HB_H (TB_H + 2)
#define HB_W (TB_W + 2)
#define TB_THREADS (TB_H * TB_W)   // 256

__global__ __launch_bounds__(TB_THREADS)
void nca_pass_b(float* __restrict__ out)
{
    __shared__ float sao[HB_H * HB_W];
    __shared__ float san[HB_H * HB_W];

    const int tid = threadIdx.x;
    int bb = blockIdx.x;
    const int tx0 = (bb % (IMG / TB_W)) * TB_W;  bb /= (IMG / TB_W);
    const int ty0 = (bb % (IMG / TB_H)) * TB_H;  bb /= (IMG / TB_H);
    const int b = bb;
    const size_t ibase = (size_t)b * IMG * IMG;

    for (int p = tid; p < HB_H * HB_W; p += TB_THREADS) {
        const int hy = ty0 + (p / HB_W) - 1;
        const int hx = tx0 + (p % HB_W) - 1;
        if ((unsigned)hy < IMG && (unsigned)hx < IMG) {
            const size_t pix = ibase + (size_t)hy * IMG + hx;
            sao[p] = g_ao[pix];
            san[p] = g_an[pix];
        } else {
            sao[p] = 0.0f;   // padding: 0 <= 0.1, equivalent to -inf for >0.1 test
            san[p] = 0.0f;
        }
    }
    __syncthreads();

    const int ty = tid / TB_W, tx = tid % TB_W;
    const int pc = (ty + 1) * HB_W + (tx + 1);

    float mo = sao[pc - HB_W - 1];
    mo = fmaxf(mo, sao[pc - HB_W]);     mo = fmaxf(mo, sao[pc - HB_W + 1]);
    mo = fmaxf(mo, sao[pc - 1]);        mo = fmaxf(mo, sao[pc]);
    mo = fmaxf(mo, sao[pc + 1]);        mo = fmaxf(mo, sao[pc + HB_W - 1]);
    mo = fmaxf(mo, sao[pc + HB_W]);     mo = fmaxf(mo, sao[pc + HB_W + 1]);

    float mn = san[pc - HB_W - 1];
    mn = fmaxf(mn, san[pc - HB_W]);     mn = fmaxf(mn, san[pc - HB_W + 1]);
    mn = fmaxf(mn, san[pc - 1]);        mn = fmaxf(mn, san[pc]);
    mn = fmaxf(mn, san[pc + 1]);        mn = fmaxf(mn, san[pc + HB_W - 1]);
    mn = fmaxf(mn, san[pc + HB_W]);     mn = fmaxf(mn, san[pc + HB_W + 1]);

    const float life = (mo > 0.1f && mn > 0.1f) ? 1.0f : 0.0f;

    const size_t pix = ibase + (size_t)(ty0 + ty) * IMG + (tx0 + tx);
    const float4* src = (const float4*)(g_xnew + pix * CH);
    float4* dst = (float4*)(out + pix * CH);
    #pragma unroll
    for (int q = 0; q < 4; q++) {
        float4 v = src[q];
        v.x *= life; v.y *= life; v.z *= life; v.w *= life;
        dst[q] = v;
    }
}

// ----------------------------------------------------------------------------
extern "C" void kernel_launch(void* const* d_in, const int* in_sizes, int n_in,
                              void* d_out, int out_size)
{
    (void)in_sizes; (void)n_in; (void)out_size;
    const float* x  = (const float*)d_in[0];
    const float* w0 = (const float*)d_in[1];
    const float* w1 = (const float*)d_in[2];
    const float* rm = (const float*)d_in[3];
    float* out = (float*)d_out;

    const int grid_a = BATCH * (IMG / TA_H) * (IMG / TA_W); // 8192
    const int grid_b = BATCH * (IMG / TB_H) * (IMG / TB_W); // 4096

    nca_pass_a<<<grid_a, TA_THREADS>>>(x, w0, w1, rm);
    nca_pass_b<<<grid_b, TB_THREADS>>>(out);
}

// round 2
// speedup vs baseline: 2.1867x; 2.1867x over previous
#include <cuda_runtime.h>
#include <math.h>
#include <stdint.h>

// ---------------------------------------------------------------------------
// Neural CA step, tensor-core version (tf32 mma.sync).
//   Pass A: perceive -> Y[128p x 48] smem -> GEMM1 (m16n128k48, per warp)
//           -> relu -> shuffle-permute acc->A frags -> GEMM2 (m16n16k128)
//           -> x_new = x + dx*(rand<=0.5); writes x_new + alpha planes.
//   Pass B: life = maxpool3x3 gating; out = x_new * life.
// ---------------------------------------------------------------------------

#define CH    16
#define NK    48
#define HID   128
#define IMG   256
#define BATCH 16

__device__ float g_xnew[(size_t)BATCH * IMG * IMG * CH]; // 64 MB
__device__ float g_an[(size_t)BATCH * IMG * IMG];
__device__ float g_ao[(size_t)BATCH * IMG * IMG];

// ------------------------------- Pass A ------------------------------------
#define TA_H 4
#define TA_W 32
#define HA_H (TA_H + 2)              // 6
#define HA_W (TA_W + 2)              // 34
#define TA_THREADS 256               // 8 warps, 16 pixels each
#define YSTRIDE 52                   // conflict-free for A-frag loads

// dynamic smem layout (bytes)
#define SX_ELEMS   (CH * HA_H * HA_W)          // 3264 floats
#define SY_ELEMS   (128 * YSTRIDE)             // 6656 u32
#define W0F_ELEMS  (6 * 16 * 32 * 2)           // 6144 u32
#define W1F_ELEMS  (16 * 2 * 32 * 2)           // 2048 u32
#define OFF_SX   0
#define OFF_SY   (OFF_SX + SX_ELEMS)
#define OFF_W0F  (OFF_SY + SY_ELEMS)
#define OFF_W1F  (OFF_W0F + W0F_ELEMS)
#define SMEM_A_BYTES ((OFF_W1F + W1F_ELEMS) * 4)   // 72448

__device__ __forceinline__ uint32_t f2tf32(float f) {
    uint32_t u;
    asm("cvt.rna.tf32.f32 %0, %1;" : "=r"(u) : "f"(f));
    return u;
}

__device__ __forceinline__ void mma_tf32(float c[4],
                                         uint32_t a0, uint32_t a1, uint32_t a2, uint32_t a3,
                                         uint32_t b0, uint32_t b1) {
    asm volatile(
        "mma.sync.aligned.m16n8k8.row.col.f32.tf32.tf32.f32 "
        "{%0,%1,%2,%3}, {%4,%5,%6,%7}, {%8,%9}, {%0,%1,%2,%3};"
        : "+f"(c[0]), "+f"(c[1]), "+f"(c[2]), "+f"(c[3])
        : "r"(a0), "r"(a1), "r"(a2), "r"(a3), "r"(b0), "r"(b1));
}

__global__ __launch_bounds__(TA_THREADS)
void nca_pass_a(const float* __restrict__ x,
                const float* __restrict__ w0,
                const float* __restrict__ w1,
                const float* __restrict__ rmask)
{
    extern __shared__ float smem[];
    float*    sx  = smem + OFF_SX;                      // [CH][HA_H*HA_W]
    uint32_t* sY  = (uint32_t*)smem + OFF_SY;           // [128][YSTRIDE] tf32
    uint32_t* w0f = (uint32_t*)smem + OFF_W0F;          // frag-packed
    uint32_t* w1f = (uint32_t*)smem + OFF_W1F;

    const int tid  = threadIdx.x;
    const int lane = tid & 31;
    const int warp = tid >> 5;
    const int tig  = lane & 3;    // thread-in-group
    const int gid  = lane >> 2;   // group id (0..7)

    // --- pack w0 fragments: w0f[((s*16+j)*32+lane)*2 + {0,1}] ---
    // b0 = B[k=8s+tig][n=8j+gid] = w0[n*48+k], b1 = k+4
    for (int idx = tid; idx < 6 * 16 * 32; idx += TA_THREADS) {
        const int l = idx & 31, jj = (idx >> 5) & 15, s = idx >> 9;
        const int k = 8 * s + (l & 3);
        const int n = 8 * jj + (l >> 2);
        w0f[idx * 2 + 0] = f2tf32(w0[n * NK + k]);
        w0f[idx * 2 + 1] = f2tf32(w0[n * NK + k + 4]);
    }
    // --- pack w1 fragments: w1f[((s*2+jj)*32+lane)*2 + {0,1}] ---
    // b0 = w1[n=8jj+gid][k=8s+tig]
    for (int idx = tid; idx < 16 * 2 * 32; idx += TA_THREADS) {
        const int l = idx & 31, jj = (idx >> 5) & 1, s = idx >> 6;
        const int k = 8 * s + (l & 3);
        const int n = 8 * jj + (l >> 2);
        w1f[idx * 2 + 0] = f2tf32(w1[n * HID + k]);
        w1f[idx * 2 + 1] = f2tf32(w1[n * HID + k + 4]);
    }

    // --- block -> (b, ty0, tx0) ---
    int bb = blockIdx.x;
    const int tx0 = (bb % (IMG / TA_W)) * TA_W;  bb /= (IMG / TA_W);
    const int ty0 = (bb % (IMG / TA_H)) * TA_H;  bb /= (IMG / TA_H);
    const int b = bb;
    const float* ximg = x + (size_t)b * IMG * IMG * CH;

    // --- halo tile load (zero pad) ---
    for (int p = tid; p < HA_H * HA_W; p += TA_THREADS) {
        const int hy = ty0 + (p / HA_W) - 1;
        const int hx = tx0 + (p % HA_W) - 1;
        if ((unsigned)hy < IMG && (unsigned)hx < IMG) {
            const float4* src = (const float4*)(ximg + ((size_t)hy * IMG + hx) * CH);
            #pragma unroll
            for (int q = 0; q < 4; q++) {
                float4 v = src[q];
                sx[(4*q + 0) * (HA_H*HA_W) + p] = v.x;
                sx[(4*q + 1) * (HA_H*HA_W) + p] = v.y;
                sx[(4*q + 2) * (HA_H*HA_W) + p] = v.z;
                sx[(4*q + 3) * (HA_H*HA_W) + p] = v.w;
            }
        } else {
            #pragma unroll
            for (int c = 0; c < CH; c++) sx[c * (HA_H*HA_W) + p] = 0.0f;
        }
    }
    __syncthreads();

    // --- perceive into sY (tf32): thread -> (pixel tid>>1, channel half tid&1)
    {
        const int p    = tid >> 1;
        const int half = tid & 1;
        const int pty = p >> 5, ptx = p & 31;
        const int pc = (pty + 1) * HA_W + (ptx + 1);
        #pragma unroll
        for (int ci = 0; ci < 8; ci++) {
            const int c = 8 * half + ci;
            const float* sp = sx + c * (HA_H*HA_W);
            const float nw = sp[pc - HA_W - 1], nn = sp[pc - HA_W], ne = sp[pc - HA_W + 1];
            const float ww = sp[pc - 1],        cc = sp[pc],        ee = sp[pc + 1];
            const float sw = sp[pc + HA_W - 1], ss = sp[pc + HA_W], se = sp[pc + HA_W + 1];
            uint32_t* yr = sY + p * YSTRIDE + 3 * c;
            yr[0] = f2tf32(cc);
            yr[1] = f2tf32(((ne + se) - (nw + sw) + 2.0f * (ee - ww)) * 0.125f);
            yr[2] = f2tf32(((sw + se) - (nw + ne) + 2.0f * (ss - nn)) * 0.125f);
        }
    }
    __syncthreads();

    // --- GEMM1: H[16p x 128] = Y * W0^T, per warp ---
    const int pbase = warp * 16;
    uint32_t a1f[6][4];
    #pragma unroll
    for (int s = 0; s < 6; s++) {
        const int col = 8 * s + tig;
        a1f[s][0] = sY[(pbase + gid)     * YSTRIDE + col];
        a1f[s][1] = sY[(pbase + gid + 8) * YSTRIDE + col];
        a1f[s][2] = sY[(pbase + gid)     * YSTRIDE + col + 4];
        a1f[s][3] = sY[(pbase + gid + 8) * YSTRIDE + col + 4];
    }

    float acc[16][4];
    #pragma unroll
    for (int j = 0; j < 16; j++)
        #pragma unroll
        for (int q = 0; q < 4; q++) acc[j][q] = 0.0f;

    #pragma unroll
    for (int j = 0; j < 16; j++) {
        #pragma unroll
        for (int s = 0; s < 6; s++) {
            const uint2 bfr = ((const uint2*)w0f)[(s * 16 + j) * 32 + lane];
            mma_tf32(acc[j], a1f[s][0], a1f[s][1], a1f[s][2], a1f[s][3], bfr.x, bfr.y);
        }
    }

    // --- relu + tf32 + quad-shuffle: acc (m16n8 C-layout) -> A-frag (m16k8) ---
    // col t held by quad-thread t>>1 (reg parity t&1); col t+4 by (t>>1)+2.
    uint32_t af[16][4];
    const unsigned fullm = 0xffffffffu;
    const int q0 = (lane & ~3) | (tig >> 1);
    const int q1 = q0 + 2;
    const bool odd = (tig & 1);
    #pragma unroll
    for (int j = 0; j < 16; j++) {
        const uint32_t u0 = f2tf32(fmaxf(acc[j][0], 0.0f));
        const uint32_t u1 = f2tf32(fmaxf(acc[j][1], 0.0f));
        const uint32_t u2 = f2tf32(fmaxf(acc[j][2], 0.0f));
        const uint32_t u3 = f2tf32(fmaxf(acc[j][3], 0.0f));
        const uint32_t p00 = __shfl_sync(fullm, u0, q0), p01 = __shfl_sync(fullm, u1, q0);
        const uint32_t p20 = __shfl_sync(fullm, u2, q0), p21 = __shfl_sync(fullm, u3, q0);
        const uint32_t r00 = __shfl_sync(fullm, u0, q1), r01 = __shfl_sync(fullm, u1, q1);
        const uint32_t r20 = __shfl_sync(fullm, u2, q1), r21 = __shfl_sync(fullm, u3, q1);
        af[j][0] = odd ? p01 : p00;   // row g,   col tig
        af[j][1] = odd ? p21 : p20;   // row g+8, col tig
        af[j][2] = odd ? r01 : r00;   // row g,   col tig+4
        af[j][3] = odd ? r21 : r20;   // row g+8, col tig+4
    }

    // --- GEMM2: dx[16p x 16] = H * W1^T ---
    float d[2][4];
    #pragma unroll
    for (int jj = 0; jj < 2; jj++)
        #pragma unroll
        for (int q = 0; q < 4; q++) d[jj][q] = 0.0f;

    #pragma unroll
    for (int jj = 0; jj < 2; jj++) {
        #pragma unroll
        for (int s = 0; s < 16; s++) {
            const uint2 bfr = ((const uint2*)w1f)[(s * 2 + jj) * 32 + lane];
            mma_tf32(d[jj], af[s][0], af[s][1], af[s][2], af[s][3], bfr.x, bfr.y);
        }
    }

    // --- epilogue: x_new = x + dx*(rand<=0.5); write x_new + alphas ---
    // thread holds pixels (g, g+8) x channels {8jj+2tig, +1}
    const int pty = warp >> 1;                 // tile row (same for both pixels)
    const int gy  = ty0 + pty;
    #pragma unroll
    for (int rr = 0; rr < 2; rr++) {
        const int r  = gid + 8 * rr;
        const int ptx = ((warp & 1) << 4) + r;
        const int gx = tx0 + ptx;
        const int pc = (pty + 1) * HA_W + (ptx + 1);
        const size_t pix = ((size_t)b * IMG + gy) * IMG + gx;
        const float upd = (rmask[pix] <= 0.5f) ? 1.0f : 0.0f;
        #pragma unroll
        for (int jj = 0; jj < 2; jj++) {
            const int ch = 8 * jj + 2 * tig;
            const float xv0 = sx[ch * (HA_H*HA_W) + pc];
            const float xv1 = sx[(ch + 1) * (HA_H*HA_W) + pc];
            float2 v;
            v.x = xv0 + d[jj][2 * rr + 0] * upd;
            v.y = xv1 + d[jj][2 * rr + 1] * upd;
            *(float2*)(g_xnew + pix * CH + ch) = v;
            if (jj == 0 && tig == 1) {          // ch pair (2,3): alpha = .y
                g_an[pix] = v.y;
                g_ao[pix] = xv1;
            }
        }
    }
}

// ------------------------------- Pass B ------------------------------------
#define TB_H 8
#define TB_W 32
#define HB_H (TB_H + 2)
#define HB_W (TB_W + 2)
#define TB_THREADS (TB_H * TB_W)   // 256

__global__ __launch_bounds__(TB_THREADS)
void nca_pass_b(float* __restrict__ out)
{
    __shared__ float sao[HB_H * HB_W];
    __shared__ float san[HB_H * HB_W];

    const int tid = threadIdx.x;
    int bb = blockIdx.x;
    const int tx0 = (bb % (IMG / TB_W)) * TB_W;  bb /= (IMG / TB_W);
    const int ty0 = (bb % (IMG / TB_H)) * TB_H;  bb /= (IMG / TB_H);
    const int b = bb;
    const size_t ibase = (size_t)b * IMG * IMG;

    for (int p = tid; p < HB_H * HB_W; p += TB_THREADS) {
        const int hy = ty0 + (p / HB_W) - 1;
        const int hx = tx0 + (p % HB_W) - 1;
        if ((unsigned)hy < IMG && (unsigned)hx < IMG) {
            const size_t pix = ibase + (size_t)hy * IMG + hx;
            sao[p] = g_ao[pix];
            san[p] = g_an[pix];
        } else {
            sao[p] = 0.0f;
            san[p] = 0.0f;
        }
    }
    __syncthreads();

    const int ty = tid / TB_W, tx = tid % TB_W;
    const int pc = (ty + 1) * HB_W + (tx + 1);

    float mo = sao[pc - HB_W - 1];
    mo = fmaxf(mo, sao[pc - HB_W]);     mo = fmaxf(mo, sao[pc - HB_W + 1]);
    mo = fmaxf(mo, sao[pc - 1]);        mo = fmaxf(mo, sao[pc]);
    mo = fmaxf(mo, sao[pc + 1]);        mo = fmaxf(mo, sao[pc + HB_W - 1]);
    mo = fmaxf(mo, sao[pc + HB_W]);     mo = fmaxf(mo, sao[pc + HB_W + 1]);

    float mn = san[pc - HB_W - 1];
    mn = fmaxf(mn, san[pc - HB_W]);     mn = fmaxf(mn, san[pc - HB_W + 1]);
    mn = fmaxf(mn, san[pc - 1]);        mn = fmaxf(mn, san[pc]);
    mn = fmaxf(mn, san[pc + 1]);        mn = fmaxf(mn, san[pc + HB_W - 1]);
    mn = fmaxf(mn, san[pc + HB_W]);     mn = fmaxf(mn, san[pc + HB_W + 1]);

    const float life = (mo > 0.1f && mn > 0.1f) ? 1.0f : 0.0f;

    const size_t pix = ibase + (size_t)(ty0 + ty) * IMG + (tx0 + tx);
    const float4* src = (const float4*)(g_xnew + pix * CH);
    float4* dst = (float4*)(out + pix * CH);
    #pragma unroll
    for (int q = 0; q < 4; q++) {
        float4 v = src[q];
        v.x *= life; v.y *= life; v.z *= life; v.w *= life;
        dst[q] = v;
    }
}

// ----------------------------------------------------------------------------
extern "C" void kernel_launch(void* const* d_in, const int* in_sizes, int n_in,
                              void* d_out, int out_size)
{
    (void)in_sizes; (void)n_in; (void)out_size;
    const float* x  = (const float*)d_in[0];
    const float* w0 = (const float*)d_in[1];
    const float* w1 = (const float*)d_in[2];
    const float* rm = (const float*)d_in[3];
    float* out = (float*)d_out;

    cudaFuncSetAttribute(nca_pass_a, cudaFuncAttributeMaxDynamicSharedMemorySize,
                         SMEM_A_BYTES);

    const int grid_a = BATCH * (IMG / TA_H) * (IMG / TA_W); // 8192
    const int grid_b = BATCH * (IMG / TB_H) * (IMG / TB_W); // 4096

    nca_pass_a<<<grid_a, TA_THREADS, SMEM_A_BYTES>>>(x, w0, w1, rm);
    nca_pass_b<<<grid_b, TB_THREADS>>>(out);
}

// round 3
// speedup vs baseline: 2.7782x; 1.2705x over previous
#include <cuda_runtime.h>
#include <math.h>
#include <stdint.h>

// ---------------------------------------------------------------------------
// Neural CA step, tf32 mma.sync, overhead-stripped.
//   Setup: pack w0/w1 into mma B-fragment order once (global scratch).
//   Pass A: halo tile (pixel-major q-planes) -> perceive (LDS.128) ->
//           Y[128x48] tf32 smem (permuted k) -> GEMM1 m16n128k48/warp ->
//           relu+shuffle-transpose -> GEMM2 m16n16k128 -> x_new epilogue.
//   Pass B: 3x3 maxpool life gating.
// ---------------------------------------------------------------------------

#define CH    16
#define NK    48
#define HID   128
#define IMG   256
#define BATCH 16

__device__ float g_xnew[(size_t)BATCH * IMG * IMG * CH]; // 64 MB
__device__ float g_an[(size_t)BATCH * IMG * IMG];
__device__ float g_ao[(size_t)BATCH * IMG * IMG];
__device__ uint2 g_w0f[6 * 16 * 32];   // 3072 packed B-frags (GEMM1)
__device__ uint2 g_w1f[16 * 2 * 32];   // 1024 packed B-frags (GEMM2)

__device__ __forceinline__ uint32_t f2tf32(float f) {
    uint32_t u;
    asm("cvt.rna.tf32.f32 %0, %1;" : "=r"(u) : "f"(f));
    return u;
}

__device__ __forceinline__ void mma_tf32(float c[4],
                                         uint32_t a0, uint32_t a1, uint32_t a2, uint32_t a3,
                                         uint32_t b0, uint32_t b1) {
    asm volatile(
        "mma.sync.aligned.m16n8k8.row.col.f32.tf32.tf32.f32 "
        "{%0,%1,%2,%3}, {%4,%5,%6,%7}, {%8,%9}, {%0,%1,%2,%3};"
        : "+f"(c[0]), "+f"(c[1]), "+f"(c[2]), "+f"(c[3])
        : "r"(a0), "r"(a1), "r"(a2), "r"(a3), "r"(b0), "r"(b1));
}

// logical feature index -> physical slot in sY (pairs (t, t+4) adjacent)
__device__ __forceinline__ int physf(int f) {
    return (f & ~7) | ((f & 3) << 1) | ((f >> 2) & 1);
}

// ---------------------------- setup: pack weights ---------------------------
__global__ void nca_pack(const float* __restrict__ w0, const float* __restrict__ w1)
{
    const int idx = blockIdx.x * blockDim.x + threadIdx.x;
    if (idx < 6 * 16 * 32) {
        const int l = idx & 31, jj = (idx >> 5) & 15, s = idx >> 9;
        const int k = 8 * s + (l & 3);
        const int n = 8 * jj + (l >> 2);
        g_w0f[idx] = make_uint2(f2tf32(w0[n * NK + k]), f2tf32(w0[n * NK + k + 4]));
    }
    if (idx < 16 * 2 * 32) {
        const int l = idx & 31, jj = (idx >> 5) & 1, s = idx >> 6;
        const int k = 8 * s + (l & 3);
        const int n = 8 * jj + (l >> 2);
        g_w1f[idx] = make_uint2(f2tf32(w1[n * HID + k]), f2tf32(w1[n * HID + k + 4]));
    }
}

// ------------------------------- Pass A ------------------------------------
#define TA_H 4
#define TA_W 32
#define HA_H (TA_H + 2)              // 6
#define HA_W (TA_W + 2)              // 34
#define TA_THREADS 256               // 8 warps, 16 pixels each
#define HA_PIX (HA_H * HA_W)         // 204
#define SXQ 824                      // words per q-plane (204*4=816, pad 8)
#define YSTRIDE 58

// smem layout (32-bit words)
#define OFF_SX   0
#define OFF_SY   (OFF_SX + 4 * SXQ)                  // 3296
#define OFF_W0F  (OFF_SY + 128 * YSTRIDE)            // 10720
#define OFF_W1F  (OFF_W0F + 6144)                    // 16864
#define SMEM_A_WORDS (OFF_W1F + 2048)                // 18912
#define SMEM_A_BYTES (SMEM_A_WORDS * 4)              // 75648

__global__ __launch_bounds__(TA_THREADS)
void nca_pass_a(const float* __restrict__ x,
                const float* __restrict__ rmask)
{
    extern __shared__ float smem[];
    float*    sxp = smem + OFF_SX;               // [4 q-planes][204 px][4 ch]
    uint32_t* sY  = (uint32_t*)smem + OFF_SY;    // [128][YSTRIDE]
    uint32_t* w0f = (uint32_t*)smem + OFF_W0F;
    uint32_t* w1f = (uint32_t*)smem + OFF_W1F;

    const int tid  = threadIdx.x;
    const int lane = tid & 31;
    const int warp = tid >> 5;
    const int tig  = lane & 3;
    const int gid  = lane >> 2;

    // --- weight smem fill: vectorized copy of pre-packed fragments ---
    {
        const uint4* s0 = (const uint4*)g_w0f;     // 1536 uint4
        uint4* d0 = (uint4*)w0f;
        #pragma unroll
        for (int i = 0; i < 6; i++) d0[tid + 256 * i] = s0[tid + 256 * i];
        const uint4* s1 = (const uint4*)g_w1f;     // 512 uint4
        uint4* d1 = (uint4*)w1f;
        #pragma unroll
        for (int i = 0; i < 2; i++) d1[tid + 256 * i] = s1[tid + 256 * i];
    }

    // --- block -> (b, ty0, tx0) ---
    int bb = blockIdx.x;
    const int tx0 = (bb % (IMG / TA_W)) * TA_W;  bb /= (IMG / TA_W);
    const int ty0 = (bb % (IMG / TA_H)) * TA_H;  bb /= (IMG / TA_H);
    const int b = bb;
    const float* ximg = x + (size_t)b * IMG * IMG * CH;

    // --- halo tile load (pixel-major q-planes, zero pad) ---
    for (int p = tid; p < HA_PIX; p += TA_THREADS) {
        const int hy = ty0 + (p / HA_W) - 1;
        const int hx = tx0 + (p % HA_W) - 1;
        if ((unsigned)hy < IMG && (unsigned)hx < IMG) {
            const float4* src = (const float4*)(ximg + ((size_t)hy * IMG + hx) * CH);
            #pragma unroll
            for (int q = 0; q < 4; q++)
                *(float4*)(sxp + q * SXQ + p * 4) = src[q];
        } else {
            const float4 z = make_float4(0.f, 0.f, 0.f, 0.f);
            #pragma unroll
            for (int q = 0; q < 4; q++)
                *(float4*)(sxp + q * SXQ + p * 4) = z;
        }
    }
    __syncthreads();

    // --- perceive: 2 threads/pixel, float4 taps, write tf32 features ---
    {
        const int p    = tid >> 1;
        const int half = tid & 1;
        const int pty = p >> 5, ptx = p & 31;
        const int pcen = (pty + 1) * HA_W + (ptx + 1);
        uint32_t* yrow = sY + p * YSTRIDE;

        #pragma unroll
        for (int qq = 0; qq < 2; qq++) {
            const int q = 2 * half + qq;
            const float* pl = sxp + q * SXQ;
            const float4 v00 = *(const float4*)(pl + (pcen - HA_W - 1) * 4);
            const float4 v01 = *(const float4*)(pl + (pcen - HA_W    ) * 4);
            const float4 v02 = *(const float4*)(pl + (pcen - HA_W + 1) * 4);
            const float4 v10 = *(const float4*)(pl + (pcen        - 1) * 4);
            const float4 v11 = *(const float4*)(pl + (pcen           ) * 4);
            const float4 v12 = *(const float4*)(pl + (pcen        + 1) * 4);
            const float4 v20 = *(const float4*)(pl + (pcen + HA_W - 1) * 4);
            const float4 v21 = *(const float4*)(pl + (pcen + HA_W    ) * 4);
            const float4 v22 = *(const float4*)(pl + (pcen + HA_W + 1) * 4);

            #define NCA_SOB(MEM, RI)                                                  \
            {                                                                         \
                const int c = 4 * q + RI;                                             \
                const float sxv = ((v02.MEM + v22.MEM) - (v00.MEM + v20.MEM)          \
                                   + 2.0f * (v12.MEM - v10.MEM)) * 0.125f;            \
                const float syv = ((v20.MEM + v22.MEM) - (v00.MEM + v02.MEM)          \
                                   + 2.0f * (v21.MEM - v01.MEM)) * 0.125f;            \
                yrow[physf(3 * c + 0)] = f2tf32(v11.MEM);                             \
                yrow[physf(3 * c + 1)] = f2tf32(sxv);                                 \
                yrow[physf(3 * c + 2)] = f2tf32(syv);                                 \
            }
            NCA_SOB(x, 0) NCA_SOB(y, 1) NCA_SOB(z, 2) NCA_SOB(w, 3)
            #undef NCA_SOB
        }
    }
    __syncthreads();

    // --- GEMM1: H[16p x 128] = Y * W0^T, per warp ---
    const int pbase = warp * 16;
    uint32_t a1f[6][4];
    #pragma unroll
    for (int s = 0; s < 6; s++) {
        const uint2 lo = *(const uint2*)(sY + (pbase + gid)     * YSTRIDE + 8 * s + 2 * tig);
        const uint2 hi = *(const uint2*)(sY + (pbase + gid + 8) * YSTRIDE + 8 * s + 2 * tig);
        a1f[s][0] = lo.x;  a1f[s][1] = hi.x;   // logical k = 8s+tig
        a1f[s][2] = lo.y;  a1f[s][3] = hi.y;   // logical k = 8s+tig+4
    }

    float acc[16][4];
    #pragma unroll
    for (int j = 0; j < 16; j++)
        #pragma unroll
        for (int q = 0; q < 4; q++) acc[j][q] = 0.0f;

    #pragma unroll
    for (int j = 0; j < 16; j++) {
        #pragma unroll
        for (int s = 0; s < 6; s++) {
            const uint2 bfr = ((const uint2*)w0f)[(s * 16 + j) * 32 + lane];
            mma_tf32(acc[j], a1f[s][0], a1f[s][1], a1f[s][2], a1f[s][3], bfr.x, bfr.y);
        }
    }

    // --- relu + tf32 + quad-shuffle: C(m16n8) -> A-frag(m16k8) ---
    uint32_t af[16][4];
    const unsigned fullm = 0xffffffffu;
    const int q0 = (lane & ~3) | (tig >> 1);
    const int q1 = q0 + 2;
    const bool odd = (tig & 1);
    #pragma unroll
    for (int j = 0; j < 16; j++) {
        const uint32_t u0 = f2tf32(fmaxf(acc[j][0], 0.0f));
        const uint32_t u1 = f2tf32(fmaxf(acc[j][1], 0.0f));
        const uint32_t u2 = f2tf32(fmaxf(acc[j][2], 0.0f));
        const uint32_t u3 = f2tf32(fmaxf(acc[j][3], 0.0f));
        const uint32_t p00 = __shfl_sync(fullm, u0, q0), p01 = __shfl_sync(fullm, u1, q0);
        const uint32_t p20 = __shfl_sync(fullm, u2, q0), p21 = __shfl_sync(fullm, u3, q0);
        const uint32_t r00 = __shfl_sync(fullm, u0, q1), r01 = __shfl_sync(fullm, u1, q1);
        const uint32_t r20 = __shfl_sync(fullm, u2, q1), r21 = __shfl_sync(fullm, u3, q1);
        af[j][0] = odd ? p01 : p00;
        af[j][1] = odd ? p21 : p20;
        af[j][2] = odd ? r01 : r00;
        af[j][3] = odd ? r21 : r20;
    }

    // --- GEMM2: dx[16p x 16] = H * W1^T ---
    float d[2][4];
    #pragma unroll
    for (int jj = 0; jj < 2; jj++)
        #pragma unroll
        for (int q = 0; q < 4; q++) d[jj][q] = 0.0f;

    #pragma unroll
    for (int jj = 0; jj < 2; jj++) {
        #pragma unroll
        for (int s = 0; s < 16; s++) {
            const uint2 bfr = ((const uint2*)w1f)[(s * 2 + jj) * 32 + lane];
            mma_tf32(d[jj], af[s][0], af[s][1], af[s][2], af[s][3], bfr.x, bfr.y);
        }
    }

    // --- epilogue ---
    const int pty = warp >> 1;
    const int gy  = ty0 + pty;
    #pragma unroll
    for (int rr = 0; rr < 2; rr++) {
        const int r  = gid + 8 * rr;
        const int ptx = ((warp & 1) << 4) + r;
        const int gx = tx0 + ptx;
        const int pc = (pty + 1) * HA_W + (ptx + 1);
        const size_t pix = ((size_t)b * IMG + gy) * IMG + gx;
        const float upd = (rmask[pix] <= 0.5f) ? 1.0f : 0.0f;
        #pragma unroll
        for (int jj = 0; jj < 2; jj++) {
            const int ch = 8 * jj + 2 * tig;
            const int q = ch >> 2, rm2 = ch & 3;
            const float2 xv = *(const float2*)(sxp + q * SXQ + pc * 4 + rm2);
            float2 v;
            v.x = xv.x + d[jj][2 * rr + 0] * upd;
            v.y = xv.y + d[jj][2 * rr + 1] * upd;
            *(float2*)(g_xnew + pix * CH + ch) = v;
            if (jj == 0 && tig == 1) {           // ch pair (2,3): alpha = .y
                g_an[pix] = v.y;
                g_ao[pix] = xv.y;
            }
        }
    }
}

// ------------------------------- Pass B ------------------------------------
#define TB_H 8
#define TB_W 32
#define HB_H (TB_H + 2)
#define HB_W (TB_W + 2)
#define TB_THREADS (TB_H * TB_W)   // 256

__global__ __launch_bounds__(TB_THREADS)
void nca_pass_b(float* __restrict__ out)
{
    __shared__ float sao[HB_H * HB_W];
    __shared__ float san[HB_H * HB_W];

    const int tid = threadIdx.x;
    int bb = blockIdx.x;
    const int tx0 = (bb % (IMG / TB_W)) * TB_W;  bb /= (IMG / TB_W);
    const int ty0 = (bb % (IMG / TB_H)) * TB_H;  bb /= (IMG / TB_H);
    const int b = bb;
    const size_t ibase = (size_t)b * IMG * IMG;

    for (int p = tid; p < HB_H * HB_W; p += TB_THREADS) {
        const int hy = ty0 + (p / HB_W) - 1;
        const int hx = tx0 + (p % HB_W) - 1;
        if ((unsigned)hy < IMG && (unsigned)hx < IMG) {
            const size_t pix = ibase + (size_t)hy * IMG + hx;
            sao[p] = g_ao[pix];
            san[p] = g_an[pix];
        } else {
            sao[p] = 0.0f;
            san[p] = 0.0f;
        }
    }
    __syncthreads();

    const int ty = tid / TB_W, tx = tid % TB_W;
    const int pc = (ty + 1) * HB_W + (tx + 1);

    float mo = sao[pc - HB_W - 1];
    mo = fmaxf(mo, sao[pc - HB_W]);     mo = fmaxf(mo, sao[pc - HB_W + 1]);
    mo = fmaxf(mo, sao[pc - 1]);        mo = fmaxf(mo, sao[pc]);
    mo = fmaxf(mo, sao[pc + 1]);        mo = fmaxf(mo, sao[pc + HB_W - 1]);
    mo = fmaxf(mo, sao[pc + HB_W]);     mo = fmaxf(mo, sao[pc + HB_W + 1]);

    float mn = san[pc - HB_W - 1];
    mn = fmaxf(mn, san[pc - HB_W]);     mn = fmaxf(mn, san[pc - HB_W + 1]);
    mn = fmaxf(mn, san[pc - 1]);        mn = fmaxf(mn, san[pc]);
    mn = fmaxf(mn, san[pc + 1]);        mn = fmaxf(mn, san[pc + HB_W - 1]);
    mn = fmaxf(mn, san[pc + HB_W]);     mn = fmaxf(mn, san[pc + HB_W + 1]);

    const float life = (mo > 0.1f && mn > 0.1f) ? 1.0f : 0.0f;

    const size_t pix = ibase + (size_t)(ty0 + ty) * IMG + (tx0 + tx);
    const float4* src = (const float4*)(g_xnew + pix * CH);
    float4* dst = (float4*)(out + pix * CH);
    #pragma unroll
    for (int q = 0; q < 4; q++) {
        float4 v = src[q];
        v.x *= life; v.y *= life; v.z *= life; v.w *= life;
        dst[q] = v;
    }
}

// ----------------------------------------------------------------------------
extern "C" void kernel_launch(void* const* d_in, const int* in_sizes, int n_in,
                              void* d_out, int out_size)
{
    (void)in_sizes; (void)n_in; (void)out_size;
    const float* x  = (const float*)d_in[0];
    const float* w0 = (const float*)d_in[1];
    const float* w1 = (const float*)d_in[2];
    const float* rm = (const float*)d_in[3];
    float* out = (float*)d_out;

    cudaFuncSetAttribute(nca_pass_a, cudaFuncAttributeMaxDynamicSharedMemorySize,
                         SMEM_A_BYTES);

    const int grid_a = BATCH * (IMG / TA_H) * (IMG / TA_W); // 8192
    const int grid_b = BATCH * (IMG / TB_H) * (IMG / TB_W); // 4096

    nca_pack<<<12, 256>>>(w0, w1);
    nca_pass_a<<<grid_a, TA_THREADS, SMEM_A_BYTES>>>(x, rm);
    nca_pass_b<<<grid_b, TB_THREADS>>>(out);
}

// round 4
// speedup vs baseline: 4.2279x; 1.5218x over previous
#include <cuda_runtime.h>
#include <cuda_fp16.h>
#include <math.h>
#include <stdint.h>

// ---------------------------------------------------------------------------
// Neural CA step, fp16 mma.sync (m16n8k16), fp32 accumulate.
//   Setup: pack w0/w1 into fp16 B-fragment order once.
//   Pass A: halo tile -> perceive -> Y[128x48] half2 smem (word-permuted) ->
//           GEMM1 m16n128k48/warp -> relu+pack (no shuffles!) ->
//           GEMM2 m16n16k128 -> x_new epilogue.
//   Pass B: 3x3 maxpool life gating.
// ---------------------------------------------------------------------------

#define CH    16
#define NK    48
#define HID   128
#define IMG   256
#define BATCH 16

__device__ float g_xnew[(size_t)BATCH * IMG * IMG * CH]; // 64 MB
__device__ float g_an[(size_t)BATCH * IMG * IMG];
__device__ float g_ao[(size_t)BATCH * IMG * IMG];
__device__ uint2 g_w0f[3 * 16 * 32];   // 1536 packed B-frags (GEMM1)
__device__ uint2 g_w1f[8 * 2 * 32];    // 512  packed B-frags (GEMM2)

__device__ __forceinline__ uint32_t pk2h(float lo, float hi) {
    __half2 h = __floats2half2_rn(lo, hi);     // .x = lo (low half)
    return *(uint32_t*)&h;
}

__device__ __forceinline__ void mma_f16(float c[4],
                                        uint32_t a0, uint32_t a1, uint32_t a2, uint32_t a3,
                                        uint32_t b0, uint32_t b1) {
    asm volatile(
        "mma.sync.aligned.m16n8k16.row.col.f32.f16.f16.f32 "
        "{%0,%1,%2,%3}, {%4,%5,%6,%7}, {%8,%9}, {%0,%1,%2,%3};"
        : "+f"(c[0]), "+f"(c[1]), "+f"(c[2]), "+f"(c[3])
        : "r"(a0), "r"(a1), "r"(a2), "r"(a3), "r"(b0), "r"(b1));
}

// logical Y word index (24 per row) -> physical slot: pairs (w, w+4) adjacent
__device__ __forceinline__ int physw(int w) {
    return (w & ~7) | ((w & 3) << 1) | ((w >> 2) & 1);
}

// ---------------------------- setup: pack weights ---------------------------
__global__ void nca_pack(const float* __restrict__ w0, const float* __restrict__ w1)
{
    const int idx = blockIdx.x * blockDim.x + threadIdx.x;
    // GEMM1 B-frags: b0=(k=16s+2t..+1, n=8j+g), b1=(k+8..+9, n)
    if (idx < 3 * 16 * 32) {
        const int l = idx & 31, j = (idx >> 5) & 15, s = idx >> 9;
        const int k = 16 * s + 2 * (l & 3);
        const int n = 8 * j + (l >> 2);
        g_w0f[idx] = make_uint2(pk2h(w0[n * NK + k],     w0[n * NK + k + 1]),
                                pk2h(w0[n * NK + k + 8], w0[n * NK + k + 9]));
    }
    // GEMM2 B-frags
    if (idx < 8 * 2 * 32) {
        const int l = idx & 31, jj = (idx >> 5) & 1, s = idx >> 6;
        const int k = 16 * s + 2 * (l & 3);
        const int n = 8 * jj + (l >> 2);
        g_w1f[idx] = make_uint2(pk2h(w1[n * HID + k],     w1[n * HID + k + 1]),
                                pk2h(w1[n * HID + k + 8], w1[n * HID + k + 9]));
    }
}

// ------------------------------- Pass A ------------------------------------
#define TA_H 4
#define TA_W 32
#define HA_H (TA_H + 2)              // 6
#define HA_W (TA_W + 2)              // 34
#define TA_THREADS 256               // 8 warps, 16 pixels each
#define HA_PIX (HA_H * HA_W)         // 204
#define SXQ 824                      // words per q-plane
#define YSTRIDE 40                   // u32 words per Y row (24 used + pad)

// smem layout (32-bit words)
#define OFF_SX   0
#define OFF_SY   (OFF_SX + 4 * SXQ)                  // 3296
#define OFF_W0F  (OFF_SY + 128 * YSTRIDE)            // 8416
#define OFF_W1F  (OFF_W0F + 3072)                    // 11488
#define SMEM_A_WORDS (OFF_W1F + 1024)                // 12512
#define SMEM_A_BYTES (SMEM_A_WORDS * 4)              // 50048

__global__ __launch_bounds__(TA_THREADS, 2)
void nca_pass_a(const float* __restrict__ x,
                const float* __restrict__ rmask)
{
    extern __shared__ float smem[];
    float*    sxp = smem + OFF_SX;               // [4 q-planes][204 px][4 ch]
    uint32_t* sY  = (uint32_t*)smem + OFF_SY;    // [128][YSTRIDE] half2 words
    uint32_t* w0f = (uint32_t*)smem + OFF_W0F;
    uint32_t* w1f = (uint32_t*)smem + OFF_W1F;

    const int tid  = threadIdx.x;
    const int lane = tid & 31;
    const int warp = tid >> 5;
    const int tig  = lane & 3;
    const int gid  = lane >> 2;

    // --- weight smem fill (vectorized, pre-packed) ---
    {
        const uint4* s0 = (const uint4*)g_w0f;     // 768 uint4
        uint4* d0 = (uint4*)w0f;
        #pragma unroll
        for (int i = 0; i < 3; i++) d0[tid + 256 * i] = s0[tid + 256 * i];
        ((uint4*)w1f)[tid] = ((const uint4*)g_w1f)[tid];   // 256 uint4
    }

    // --- block -> (b, ty0, tx0) ---
    int bb = blockIdx.x;
    const int tx0 = (bb % (IMG / TA_W)) * TA_W;  bb /= (IMG / TA_W);
    const int ty0 = (bb % (IMG / TA_H)) * TA_H;  bb /= (IMG / TA_H);
    const int b = bb;
    const float* ximg = x + (size_t)b * IMG * IMG * CH;

    // --- halo tile load (pixel-major q-planes, zero pad) ---
    for (int p = tid; p < HA_PIX; p += TA_THREADS) {
        const int hy = ty0 + (p / HA_W) - 1;
        const int hx = tx0 + (p % HA_W) - 1;
        if ((unsigned)hy < IMG && (unsigned)hx < IMG) {
            const float4* src = (const float4*)(ximg + ((size_t)hy * IMG + hx) * CH);
            #pragma unroll
            for (int q = 0; q < 4; q++)
                *(float4*)(sxp + q * SXQ + p * 4) = src[q];
        } else {
            const float4 z = make_float4(0.f, 0.f, 0.f, 0.f);
            #pragma unroll
            for (int q = 0; q < 4; q++)
                *(float4*)(sxp + q * SXQ + p * 4) = z;
        }
    }
    __syncthreads();

    // --- perceive: 2 threads/pixel, 8 channels each -> 24 features -> 12 words
    {
        const int p    = tid >> 1;
        const int half = tid & 1;
        const int pty = p >> 5, ptx = p & 31;
        const int pcen = (pty + 1) * HA_W + (ptx + 1);
        uint32_t* yrow = sY + p * YSTRIDE;

        float feat[24];
        #pragma unroll
        for (int qq = 0; qq < 2; qq++) {
            const int q = 2 * half + qq;
            const float* pl = sxp + q * SXQ;
            const float4 v00 = *(const float4*)(pl + (pcen - HA_W - 1) * 4);
            const float4 v01 = *(const float4*)(pl + (pcen - HA_W    ) * 4);
            const float4 v02 = *(const float4*)(pl + (pcen - HA_W + 1) * 4);
            const float4 v10 = *(const float4*)(pl + (pcen        - 1) * 4);
            const float4 v11 = *(const float4*)(pl + (pcen           ) * 4);
            const float4 v12 = *(const float4*)(pl + (pcen        + 1) * 4);
            const float4 v20 = *(const float4*)(pl + (pcen + HA_W - 1) * 4);
            const float4 v21 = *(const float4*)(pl + (pcen + HA_W    ) * 4);
            const float4 v22 = *(const float4*)(pl + (pcen + HA_W + 1) * 4);

            #define NCA_SOB(MEM, RI)                                                  \
            {                                                                         \
                const int fb = 3 * (4 * qq + RI);                                     \
                feat[fb + 0] = v11.MEM;                                               \
                feat[fb + 1] = ((v02.MEM + v22.MEM) - (v00.MEM + v20.MEM)             \
                                + 2.0f * (v12.MEM - v10.MEM)) * 0.125f;               \
                feat[fb + 2] = ((v20.MEM + v22.MEM) - (v00.MEM + v02.MEM)             \
                                + 2.0f * (v21.MEM - v01.MEM)) * 0.125f;               \
            }
            NCA_SOB(x, 0) NCA_SOB(y, 1) NCA_SOB(z, 2) NCA_SOB(w, 3)
            #undef NCA_SOB
        }
        const int wbase = 12 * half;   // logical word offset
        #pragma unroll
        for (int wl = 0; wl < 12; wl++)
            yrow[physw(wbase + wl)] = pk2h(feat[2 * wl], feat[2 * wl + 1]);
    }
    __syncthreads();

    // --- A-fragments for GEMM1 (LDS.64, conflict-free) ---
    const int pbase = warp * 16;
    uint32_t a1f[3][4];
    #pragma unroll
    for (int s = 0; s < 3; s++) {
        const uint2 lo = *(const uint2*)(sY + (pbase + gid)     * YSTRIDE + 8 * s + 2 * tig);
        const uint2 hi = *(const uint2*)(sY + (pbase + gid + 8) * YSTRIDE + 8 * s + 2 * tig);
        a1f[s][0] = lo.x;  a1f[s][1] = hi.x;   // k pair (16s+2t, +1), rows g / g+8
        a1f[s][2] = lo.y;  a1f[s][3] = hi.y;   // k pair (16s+2t+8, +9)
    }

    // --- GEMM1 + relu + pack directly into GEMM2 A-frags (no shuffles) ---
    uint32_t af[8][4];
    #pragma unroll
    for (int s2 = 0; s2 < 8; s2++) {
        float acc0[4] = {0.f, 0.f, 0.f, 0.f};
        float acc1[4] = {0.f, 0.f, 0.f, 0.f};
        #pragma unroll
        for (int s = 0; s < 3; s++) {
            const uint2 b0 = ((const uint2*)w0f)[(s * 16 + 2 * s2)     * 32 + lane];
            const uint2 b1 = ((const uint2*)w0f)[(s * 16 + 2 * s2 + 1) * 32 + lane];
            mma_f16(acc0, a1f[s][0], a1f[s][1], a1f[s][2], a1f[s][3], b0.x, b0.y);
            mma_f16(acc1, a1f[s][0], a1f[s][1], a1f[s][2], a1f[s][3], b1.x, b1.y);
        }
        af[s2][0] = pk2h(fmaxf(acc0[0], 0.f), fmaxf(acc0[1], 0.f));  // H[g][16s2+2t..]
        af[s2][1] = pk2h(fmaxf(acc0[2], 0.f), fmaxf(acc0[3], 0.f));  // H[g+8][...]
        af[s2][2] = pk2h(fmaxf(acc1[0], 0.f), fmaxf(acc1[1], 0.f));  // k+8 pair
        af[s2][3] = pk2h(fmaxf(acc1[2], 0.f), fmaxf(acc1[3], 0.f));
    }

    // --- GEMM2: dx[16p x 16] = H * W1^T ---
    float d[2][4];
    #pragma unroll
    for (int jj = 0; jj < 2; jj++)
        #pragma unroll
        for (int q = 0; q < 4; q++) d[jj][q] = 0.0f;

    #pragma unroll
    for (int jj = 0; jj < 2; jj++) {
        #pragma unroll
        for (int s = 0; s < 8; s++) {
            const uint2 bfr = ((const uint2*)w1f)[(s * 2 + jj) * 32 + lane];
            mma_f16(d[jj], af[s][0], af[s][1], af[s][2], af[s][3], bfr.x, bfr.y);
        }
    }

    // --- epilogue: x_new = x + dx*(rand<=0.5) ---
    const int pty = warp >> 1;
    const int gy  = ty0 + pty;
    #pragma unroll
    for (int rr = 0; rr < 2; rr++) {
        const int r  = gid + 8 * rr;
        const int ptx = ((warp & 1) << 4) + r;
        const int gx = tx0 + ptx;
        const int pc = (pty + 1) * HA_W + (ptx + 1);
        const size_t pix = ((size_t)b * IMG + gy) * IMG + gx;
        const float upd = (rmask[pix] <= 0.5f) ? 1.0f : 0.0f;
        #pragma unroll
        for (int jj = 0; jj < 2; jj++) {
            const int ch = 8 * jj + 2 * tig;
            const int q = ch >> 2, rm2 = ch & 3;
            const float2 xv = *(const float2*)(sxp + q * SXQ + pc * 4 + rm2);
            float2 v;
            v.x = xv.x + d[jj][2 * rr + 0] * upd;
            v.y = xv.y + d[jj][2 * rr + 1] * upd;
            *(float2*)(g_xnew + pix * CH + ch) = v;
            if (jj == 0 && tig == 1) {           // ch pair (2,3): alpha = .y
                g_an[pix] = v.y;
                g_ao[pix] = xv.y;
            }
        }
    }
}

// ------------------------------- Pass B ------------------------------------
#define TB_H 8
#define TB_W 32
#define HB_H (TB_H + 2)
#define HB_W (TB_W + 2)
#define TB_THREADS (TB_H * TB_W)   // 256

__global__ __launch_bounds__(TB_THREADS)
void nca_pass_b(float* __restrict__ out)
{
    __shared__ float sao[HB_H * HB_W];
    __shared__ float san[HB_H * HB_W];

    const int tid = threadIdx.x;
    int bb = blockIdx.x;
    const int tx0 = (bb % (IMG / TB_W)) * TB_W;  bb /= (IMG / TB_W);
    const int ty0 = (bb % (IMG / TB_H)) * TB_H;  bb /= (IMG / TB_H);
    const int b = bb;
    const size_t ibase = (size_t)b * IMG * IMG;

    for (int p = tid; p < HB_H * HB_W; p += TB_THREADS) {
        const int hy = ty0 + (p / HB_W) - 1;
        const int hx = tx0 + (p % HB_W) - 1;
        if ((unsigned)hy < IMG && (unsigned)hx < IMG) {
            const size_t pix = ibase + (size_t)hy * IMG + hx;
            sao[p] = g_ao[pix];
            san[p] = g_an[pix];
        } else {
            sao[p] = 0.0f;
            san[p] = 0.0f;
        }
    }
    __syncthreads();

    const int ty = tid / TB_W, tx = tid % TB_W;
    const int pc = (ty + 1) * HB_W + (tx + 1);

    float mo = sao[pc - HB_W - 1];
    mo = fmaxf(mo, sao[pc - HB_W]);     mo = fmaxf(mo, sao[pc - HB_W + 1]);
    mo = fmaxf(mo, sao[pc - 1]);        mo = fmaxf(mo, sao[pc]);
    mo = fmaxf(mo, sao[pc + 1]);        mo = fmaxf(mo, sao[pc + HB_W - 1]);
    mo = fmaxf(mo, sao[pc + HB_W]);     mo = fmaxf(mo, sao[pc + HB_W + 1]);

    float mn = san[pc - HB_W - 1];
    mn = fmaxf(mn, san[pc - HB_W]);     mn = fmaxf(mn, san[pc - HB_W + 1]);
    mn = fmaxf(mn, san[pc - 1]);        mn = fmaxf(mn, san[pc]);
    mn = fmaxf(mn, san[pc + 1]);        mn = fmaxf(mn, san[pc + HB_W - 1]);
    mn = fmaxf(mn, san[pc + HB_W]);     mn = fmaxf(mn, san[pc + HB_W + 1]);

    const float life = (mo > 0.1f && mn > 0.1f) ? 1.0f : 0.0f;

    const size_t pix = ibase + (size_t)(ty0 + ty) * IMG + (tx0 + tx);
    const float4* src = (const float4*)(g_xnew + pix * CH);
    float4* dst = (float4*)(out + pix * CH);
    float4 v0 = src[0], v1 = src[1], v2 = src[2], v3 = src[3];
    v0.x *= life; v0.y *= life; v0.z *= life; v0.w *= life;
    v1.x *= life; v1.y *= life; v1.z *= life; v1.w *= life;
    v2.x *= life; v2.y *= life; v2.z *= life; v2.w *= life;
    v3.x *= life; v3.y *= life; v3.z *= life; v3.w *= life;
    dst[0] = v0; dst[1] = v1; dst[2] = v2; dst[3] = v3;
}

// ----------------------------------------------------------------------------
extern "C" void kernel_launch(void* const* d_in, const int* in_sizes, int n_in,
                              void* d_out, int out_size)
{
    (void)in_sizes; (void)n_in; (void)out_size;
    const float* x  = (const float*)d_in[0];
    const float* w0 = (const float*)d_in[1];
    const float* w1 = (const float*)d_in[2];
    const float* rm = (const float*)d_in[3];
    float* out = (float*)d_out;

    cudaFuncSetAttribute(nca_pass_a, cudaFuncAttributeMaxDynamicSharedMemorySize,
                         SMEM_A_BYTES);

    const int grid_a = BATCH * (IMG / TA_H) * (IMG / TA_W); // 8192
    const int grid_b = BATCH * (IMG / TB_H) * (IMG / TB_W); // 4096

    nca_pack<<<6, 256>>>(w0, w1);
    nca_pass_a<<<grid_a, TA_THREADS, SMEM_A_BYTES>>>(x, rm);
    nca_pass_b<<<grid_b, TB_THREADS>>>(out);
}

// round 5
// speedup vs baseline: 4.8960x; 1.1580x over previous
#include <cuda_runtime.h>
#include <cuda_fp16.h>
#include <math.h>
#include <stdint.h>

// ---------------------------------------------------------------------------
// Neural CA step, fp16 mma.sync (m16n8k16), fp32 accumulate.
//   Setup: pack w0/w1 into fp16 B-fragment order once.
//   Pass A: halo tile -> perceive -> Y[128x48] half2 smem (word-permuted) ->
//           GEMM1 m16n128k48/warp -> relu+pack -> GEMM2 m16n16k128 ->
//           x_new written DIRECTLY to out; alpha planes to scratch.
//   Pass B: fix-up only — compute life from alpha planes; zero dead pixels.
// ---------------------------------------------------------------------------

#define CH    16
#define NK    48
#define HID   128
#define IMG   256
#define BATCH 16

__device__ float g_an[(size_t)BATCH * IMG * IMG];
__device__ float g_ao[(size_t)BATCH * IMG * IMG];
__device__ uint2 g_w0f[3 * 16 * 32];   // 1536 packed B-frags (GEMM1)
__device__ uint2 g_w1f[8 * 2 * 32];    // 512  packed B-frags (GEMM2)

__device__ __forceinline__ uint32_t pk2h(float lo, float hi) {
    __half2 h = __floats2half2_rn(lo, hi);
    return *(uint32_t*)&h;
}

__device__ __forceinline__ void mma_f16(float c[4],
                                        uint32_t a0, uint32_t a1, uint32_t a2, uint32_t a3,
                                        uint32_t b0, uint32_t b1) {
    asm volatile(
        "mma.sync.aligned.m16n8k16.row.col.f32.f16.f16.f32 "
        "{%0,%1,%2,%3}, {%4,%5,%6,%7}, {%8,%9}, {%0,%1,%2,%3};"
        : "+f"(c[0]), "+f"(c[1]), "+f"(c[2]), "+f"(c[3])
        : "r"(a0), "r"(a1), "r"(a2), "r"(a3), "r"(b0), "r"(b1));
}

// logical Y word index (24 per row) -> physical slot: pairs (w, w+4) adjacent
__device__ __forceinline__ int physw(int w) {
    return (w & ~7) | ((w & 3) << 1) | ((w >> 2) & 1);
}

// ---------------------------- setup: pack weights ---------------------------
__global__ void nca_pack(const float* __restrict__ w0, const float* __restrict__ w1)
{
    const int idx = blockIdx.x * blockDim.x + threadIdx.x;
    if (idx < 3 * 16 * 32) {
        const int l = idx & 31, j = (idx >> 5) & 15, s = idx >> 9;
        const int k = 16 * s + 2 * (l & 3);
        const int n = 8 * j + (l >> 2);
        g_w0f[idx] = make_uint2(pk2h(w0[n * NK + k],     w0[n * NK + k + 1]),
                                pk2h(w0[n * NK + k + 8], w0[n * NK + k + 9]));
    }
    if (idx < 8 * 2 * 32) {
        const int l = idx & 31, jj = (idx >> 5) & 1, s = idx >> 6;
        const int k = 16 * s + 2 * (l & 3);
        const int n = 8 * jj + (l >> 2);
        g_w1f[idx] = make_uint2(pk2h(w1[n * HID + k],     w1[n * HID + k + 1]),
                                pk2h(w1[n * HID + k + 8], w1[n * HID + k + 9]));
    }
}

// ------------------------------- Pass A ------------------------------------
#define TA_H 4
#define TA_W 32
#define HA_H (TA_H + 2)              // 6
#define HA_W (TA_W + 2)              // 34
#define TA_THREADS 256               // 8 warps, 16 pixels each
#define HA_PIX (HA_H * HA_W)         // 204
#define SXQ 824                      // words per q-plane
#define YSTRIDE 40                   // u32 words per Y row (24 used + pad)

// smem layout (32-bit words)
#define OFF_SX   0
#define OFF_SY   (OFF_SX + 4 * SXQ)                  // 3296
#define OFF_W0F  (OFF_SY + 128 * YSTRIDE)            // 8416
#define OFF_W1F  (OFF_W0F + 3072)                    // 11488
#define SMEM_A_WORDS (OFF_W1F + 1024)                // 12512
#define SMEM_A_BYTES (SMEM_A_WORDS * 4)              // 50048

__global__ __launch_bounds__(TA_THREADS, 2)
void nca_pass_a(const float* __restrict__ x,
                const float* __restrict__ rmask,
                float* __restrict__ out)
{
    extern __shared__ float smem[];
    float*    sxp = smem + OFF_SX;
    uint32_t* sY  = (uint32_t*)smem + OFF_SY;
    uint32_t* w0f = (uint32_t*)smem + OFF_W0F;
    uint32_t* w1f = (uint32_t*)smem + OFF_W1F;

    const int tid  = threadIdx.x;
    const int lane = tid & 31;
    const int warp = tid >> 5;
    const int tig  = lane & 3;
    const int gid  = lane >> 2;

    // --- weight smem fill (vectorized, pre-packed) ---
    {
        const uint4* s0 = (const uint4*)g_w0f;
        uint4* d0 = (uint4*)w0f;
        #pragma unroll
        for (int i = 0; i < 3; i++) d0[tid + 256 * i] = s0[tid + 256 * i];
        ((uint4*)w1f)[tid] = ((const uint4*)g_w1f)[tid];
    }

    // --- block -> (b, ty0, tx0) ---
    int bb = blockIdx.x;
    const int tx0 = (bb % (IMG / TA_W)) * TA_W;  bb /= (IMG / TA_W);
    const int ty0 = (bb % (IMG / TA_H)) * TA_H;  bb /= (IMG / TA_H);
    const int b = bb;
    const float* ximg = x + (size_t)b * IMG * IMG * CH;

    // --- halo tile load (pixel-major q-planes, zero pad) ---
    for (int p = tid; p < HA_PIX; p += TA_THREADS) {
        const int hy = ty0 + (p / HA_W) - 1;
        const int hx = tx0 + (p % HA_W) - 1;
        if ((unsigned)hy < IMG && (unsigned)hx < IMG) {
            const float4* src = (const float4*)(ximg + ((size_t)hy * IMG + hx) * CH);
            #pragma unroll
            for (int q = 0; q < 4; q++)
                *(float4*)(sxp + q * SXQ + p * 4) = src[q];
        } else {
            const float4 z = make_float4(0.f, 0.f, 0.f, 0.f);
            #pragma unroll
            for (int q = 0; q < 4; q++)
                *(float4*)(sxp + q * SXQ + p * 4) = z;
        }
    }
    __syncthreads();

    // --- perceive: 2 threads/pixel, 8 channels each -> 24 features ---
    {
        const int p    = tid >> 1;
        const int half = tid & 1;
        const int pty = p >> 5, ptx = p & 31;
        const int pcen = (pty + 1) * HA_W + (ptx + 1);
        uint32_t* yrow = sY + p * YSTRIDE;

        float feat[24];
        #pragma unroll
        for (int qq = 0; qq < 2; qq++) {
            const int q = 2 * half + qq;
            const float* pl = sxp + q * SXQ;
            const float4 v00 = *(const float4*)(pl + (pcen - HA_W - 1) * 4);
            const float4 v01 = *(const float4*)(pl + (pcen - HA_W    ) * 4);
            const float4 v02 = *(const float4*)(pl + (pcen - HA_W + 1) * 4);
            const float4 v10 = *(const float4*)(pl + (pcen        - 1) * 4);
            const float4 v11 = *(const float4*)(pl + (pcen           ) * 4);
            const float4 v12 = *(const float4*)(pl + (pcen        + 1) * 4);
            const float4 v20 = *(const float4*)(pl + (pcen + HA_W - 1) * 4);
            const float4 v21 = *(const float4*)(pl + (pcen + HA_W    ) * 4);
            const float4 v22 = *(const float4*)(pl + (pcen + HA_W + 1) * 4);

            #define NCA_SOB(MEM, RI)                                                  \
            {                                                                         \
                const int fb = 3 * (4 * qq + RI);                                     \
                feat[fb + 0] = v11.MEM;                                               \
                feat[fb + 1] = ((v02.MEM + v22.MEM) - (v00.MEM + v20.MEM)             \
                                + 2.0f * (v12.MEM - v10.MEM)) * 0.125f;               \
                feat[fb + 2] = ((v20.MEM + v22.MEM) - (v00.MEM + v02.MEM)             \
                                + 2.0f * (v21.MEM - v01.MEM)) * 0.125f;               \
            }
            NCA_SOB(x, 0) NCA_SOB(y, 1) NCA_SOB(z, 2) NCA_SOB(w, 3)
            #undef NCA_SOB
        }
        const int wbase = 12 * half;
        #pragma unroll
        for (int wl = 0; wl < 12; wl++)
            yrow[physw(wbase + wl)] = pk2h(feat[2 * wl], feat[2 * wl + 1]);
    }
    __syncthreads();

    // --- A-fragments for GEMM1 ---
    const int pbase = warp * 16;
    uint32_t a1f[3][4];
    #pragma unroll
    for (int s = 0; s < 3; s++) {
        const uint2 lo = *(const uint2*)(sY + (pbase + gid)     * YSTRIDE + 8 * s + 2 * tig);
        const uint2 hi = *(const uint2*)(sY + (pbase + gid + 8) * YSTRIDE + 8 * s + 2 * tig);
        a1f[s][0] = lo.x;  a1f[s][1] = hi.x;
        a1f[s][2] = lo.y;  a1f[s][3] = hi.y;
    }

    // --- GEMM1 + relu + pack into GEMM2 A-frags ---
    uint32_t af[8][4];
    #pragma unroll
    for (int s2 = 0; s2 < 8; s2++) {
        float acc0[4] = {0.f, 0.f, 0.f, 0.f};
        float acc1[4] = {0.f, 0.f, 0.f, 0.f};
        #pragma unroll
        for (int s = 0; s < 3; s++) {
            const uint2 b0 = ((const uint2*)w0f)[(s * 16 + 2 * s2)     * 32 + lane];
            const uint2 b1 = ((const uint2*)w0f)[(s * 16 + 2 * s2 + 1) * 32 + lane];
            mma_f16(acc0, a1f[s][0], a1f[s][1], a1f[s][2], a1f[s][3], b0.x, b0.y);
            mma_f16(acc1, a1f[s][0], a1f[s][1], a1f[s][2], a1f[s][3], b1.x, b1.y);
        }
        af[s2][0] = pk2h(fmaxf(acc0[0], 0.f), fmaxf(acc0[1], 0.f));
        af[s2][1] = pk2h(fmaxf(acc0[2], 0.f), fmaxf(acc0[3], 0.f));
        af[s2][2] = pk2h(fmaxf(acc1[0], 0.f), fmaxf(acc1[1], 0.f));
        af[s2][3] = pk2h(fmaxf(acc1[2], 0.f), fmaxf(acc1[3], 0.f));
    }

    // --- GEMM2: dx[16p x 16] = H * W1^T ---
    float d[2][4];
    #pragma unroll
    for (int jj = 0; jj < 2; jj++)
        #pragma unroll
        for (int q = 0; q < 4; q++) d[jj][q] = 0.0f;

    #pragma unroll
    for (int jj = 0; jj < 2; jj++) {
        #pragma unroll
        for (int s = 0; s < 8; s++) {
            const uint2 bfr = ((const uint2*)w1f)[(s * 2 + jj) * 32 + lane];
            mma_f16(d[jj], af[s][0], af[s][1], af[s][2], af[s][3], bfr.x, bfr.y);
        }
    }

    // --- epilogue: x_new = x + dx*(rand<=0.5) -> OUT directly ---
    const int pty = warp >> 1;
    const int gy  = ty0 + pty;
    #pragma unroll
    for (int rr = 0; rr < 2; rr++) {
        const int r  = gid + 8 * rr;
        const int ptx = ((warp & 1) << 4) + r;
        const int gx = tx0 + ptx;
        const int pc = (pty + 1) * HA_W + (ptx + 1);
        const size_t pix = ((size_t)b * IMG + gy) * IMG + gx;
        const float upd = (rmask[pix] <= 0.5f) ? 1.0f : 0.0f;
        #pragma unroll
        for (int jj = 0; jj < 2; jj++) {
            const int ch = 8 * jj + 2 * tig;
            const int q = ch >> 2, rm2 = ch & 3;
            const float2 xv = *(const float2*)(sxp + q * SXQ + pc * 4 + rm2);
            float2 v;
            v.x = xv.x + d[jj][2 * rr + 0] * upd;
            v.y = xv.y + d[jj][2 * rr + 1] * upd;
            *(float2*)(out + pix * CH + ch) = v;
            if (jj == 0 && tig == 1) {           // ch pair (2,3): alpha = .y
                g_an[pix] = v.y;
                g_ao[pix] = xv.y;
            }
        }
    }
}

// ------------------------------- Pass B (fix-up) ----------------------------
#define TB_H 8
#define TB_W 32
#define HB_H (TB_H + 2)
#define HB_W (TB_W + 2)
#define TB_THREADS (TB_H * TB_W)   // 256

__global__ __launch_bounds__(TB_THREADS)
void nca_pass_b(float* __restrict__ out)
{
    __shared__ float sao[HB_H * HB_W];
    __shared__ float san[HB_H * HB_W];

    const int tid = threadIdx.x;
    int bb = blockIdx.x;
    const int tx0 = (bb % (IMG / TB_W)) * TB_W;  bb /= (IMG / TB_W);
    const int ty0 = (bb % (IMG / TB_H)) * TB_H;  bb /= (IMG / TB_H);
    const int b = bb;
    const size_t ibase = (size_t)b * IMG * IMG;

    for (int p = tid; p < HB_H * HB_W; p += TB_THREADS) {
        const int hy = ty0 + (p / HB_W) - 1;
        const int hx = tx0 + (p % HB_W) - 1;
        if ((unsigned)hy < IMG && (unsigned)hx < IMG) {
            const size_t pix = ibase + (size_t)hy * IMG + hx;
            sao[p] = g_ao[pix];
            san[p] = g_an[pix];
        } else {
            sao[p] = 0.0f;
            san[p] = 0.0f;
        }
    }
    __syncthreads();

    const int ty = tid / TB_W, tx = tid % TB_W;
    const int pc = (ty + 1) * HB_W + (tx + 1);

    float mo = sao[pc - HB_W - 1];
    mo = fmaxf(mo, sao[pc - HB_W]);     mo = fmaxf(mo, sao[pc - HB_W + 1]);
    mo = fmaxf(mo, sao[pc - 1]);        mo = fmaxf(mo, sao[pc]);
    mo = fmaxf(mo, sao[pc + 1]);        mo = fmaxf(mo, sao[pc + HB_W - 1]);
    mo = fmaxf(mo, sao[pc + HB_W]);     mo = fmaxf(mo, sao[pc + HB_W + 1]);

    float mn = san[pc - HB_W - 1];
    mn = fmaxf(mn, san[pc - HB_W]);     mn = fmaxf(mn, san[pc - HB_W + 1]);
    mn = fmaxf(mn, san[pc - 1]);        mn = fmaxf(mn, san[pc]);
    mn = fmaxf(mn, san[pc + 1]);        mn = fmaxf(mn, san[pc + HB_W - 1]);
    mn = fmaxf(mn, san[pc + HB_W]);     mn = fmaxf(mn, san[pc + HB_W + 1]);

    // out already holds x_new; only dead pixels need zeroing.
    if (!(mo > 0.1f && mn > 0.1f)) {
        const size_t pix = ibase + (size_t)(ty0 + ty) * IMG + (tx0 + tx);
        float4* dst = (float4*)(out + pix * CH);
        const float4 z = make_float4(0.f, 0.f, 0.f, 0.f);
        dst[0] = z; dst[1] = z; dst[2] = z; dst[3] = z;
    }
}

// ----------------------------------------------------------------------------
extern "C" void kernel_launch(void* const* d_in, const int* in_sizes, int n_in,
                              void* d_out, int out_size)
{
    (void)in_sizes; (void)n_in; (void)out_size;
    const float* x  = (const float*)d_in[0];
    const float* w0 = (const float*)d_in[1];
    const float* w1 = (const float*)d_in[2];
    const float* rm = (const float*)d_in[3];
    float* out = (float*)d_out;

    cudaFuncSetAttribute(nca_pass_a, cudaFuncAttributeMaxDynamicSharedMemorySize,
                         SMEM_A_BYTES);

    const int grid_a = BATCH * (IMG / TA_H) * (IMG / TA_W); // 8192
    const int grid_b = BATCH * (IMG / TB_H) * (IMG / TB_W); // 4096

    nca_pack<<<6, 256>>>(w0, w1);
    nca_pass_a<<<grid_a, TA_THREADS, SMEM_A_BYTES>>>(x, rm, out);
    nca_pass_b<<<grid_b, TB_THREADS>>>(out);
}

// round 6
// speedup vs baseline: 5.3305x; 1.0888x over previous
#include <cuda_runtime.h>
#include <cuda_fp16.h>
#include <math.h>
#include <stdint.h>

// ---------------------------------------------------------------------------
// Neural CA step, fp16 mma.sync (m16n8k16), fp32 accumulate.
//   Setup: pack w0/w1 into uint4 B-fragment order (both n-tiles adjacent).
//   Pass A: halo tile -> perceive -> Y[128x48] half2 smem (word-permuted) ->
//           fused GEMM1(+relu+pack)->GEMM2 per 16-wide hidden slice ->
//           x_new written directly to out; alpha planes to scratch.
//   Pass B: fix-up — compute life from alpha planes; zero dead pixels only.
// ---------------------------------------------------------------------------

#define CH    16
#define NK    48
#define HID   128
#define IMG   256
#define BATCH 16

__device__ float g_an[(size_t)BATCH * IMG * IMG];
__device__ float g_ao[(size_t)BATCH * IMG * IMG];
__device__ uint2 g_w0f[3 * 8 * 32 * 2];   // uint4-pairable GEMM1 B-frags
__device__ uint2 g_w1f[8 * 32 * 2];       // uint4-pairable GEMM2 B-frags

__device__ __forceinline__ uint32_t pk2h(float lo, float hi) {
    __half2 h = __floats2half2_rn(lo, hi);
    return *(uint32_t*)&h;
}

__device__ __forceinline__ void mma_f16(float c[4],
                                        uint32_t a0, uint32_t a1, uint32_t a2, uint32_t a3,
                                        uint32_t b0, uint32_t b1) {
    asm volatile(
        "mma.sync.aligned.m16n8k16.row.col.f32.f16.f16.f32 "
        "{%0,%1,%2,%3}, {%4,%5,%6,%7}, {%8,%9}, {%0,%1,%2,%3};"
        : "+f"(c[0]), "+f"(c[1]), "+f"(c[2]), "+f"(c[3])
        : "r"(a0), "r"(a1), "r"(a2), "r"(a3), "r"(b0), "r"(b1));
}

// logical Y word index (24 per row) -> physical slot: pairs (w, w+4) adjacent
__device__ __forceinline__ int physw(int w) {
    return (w & ~7) | ((w & 3) << 1) | ((w >> 2) & 1);
}

// ---------------------------- setup: pack weights ---------------------------
__global__ void nca_pack(const float* __restrict__ w0, const float* __restrict__ w1)
{
    const int idx = blockIdx.x * blockDim.x + threadIdx.x;
    // GEMM1: uint2 element ((s*8+s2)*32+lane)*2+which ; j = 2*s2+which
    if (idx < 3 * 8 * 32 * 2) {
        const int which = idx & 1;
        const int lane  = (idx >> 1) & 31;
        const int s2    = (idx >> 6) & 7;
        const int s     = idx >> 9;
        const int j = 2 * s2 + which;
        const int k = 16 * s + 2 * (lane & 3);
        const int n = 8 * j + (lane >> 2);
        g_w0f[idx] = make_uint2(pk2h(w0[n * NK + k],     w0[n * NK + k + 1]),
                                pk2h(w0[n * NK + k + 8], w0[n * NK + k + 9]));
    }
    // GEMM2: uint2 element (s*32+lane)*2+jj
    if (idx < 8 * 32 * 2) {
        const int jj   = idx & 1;
        const int lane = (idx >> 1) & 31;
        const int s    = idx >> 6;
        const int k = 16 * s + 2 * (lane & 3);
        const int n = 8 * jj + (lane >> 2);
        g_w1f[idx] = make_uint2(pk2h(w1[n * HID + k],     w1[n * HID + k + 1]),
                                pk2h(w1[n * HID + k + 8], w1[n * HID + k + 9]));
    }
}

// ------------------------------- Pass A ------------------------------------
#define TA_H 4
#define TA_W 32
#define HA_H (TA_H + 2)              // 6
#define HA_W (TA_W + 2)              // 34
#define TA_THREADS 256               // 8 warps, 16 pixels each
#define HA_PIX (HA_H * HA_W)         // 204
#define SXQ 824                      // words per q-plane
#define YSTRIDE 40                   // u32 words per Y row (24 used + pad)

// smem layout (32-bit words)
#define OFF_SX   0
#define OFF_SY   (OFF_SX + 4 * SXQ)                  // 3296
#define OFF_W0F  (OFF_SY + 128 * YSTRIDE)            // 8416
#define OFF_W1F  (OFF_W0F + 3072)                    // 11488
#define SMEM_A_WORDS (OFF_W1F + 1024)                // 12512
#define SMEM_A_BYTES (SMEM_A_WORDS * 4)              // 50048

__global__ __launch_bounds__(TA_THREADS, 2)
void nca_pass_a(const float* __restrict__ x,
                const float* __restrict__ rmask,
                float* __restrict__ out)
{
    extern __shared__ float smem[];
    float*    sxp = smem + OFF_SX;
    uint32_t* sY  = (uint32_t*)smem + OFF_SY;
    uint32_t* w0f = (uint32_t*)smem + OFF_W0F;
    uint32_t* w1f = (uint32_t*)smem + OFF_W1F;

    const int tid  = threadIdx.x;
    const int lane = tid & 31;
    const int warp = tid >> 5;
    const int tig  = lane & 3;
    const int gid  = lane >> 2;

    // --- weight smem fill (vectorized, pre-packed) ---
    {
        const uint4* s0 = (const uint4*)g_w0f;     // 768 uint4
        uint4* d0 = (uint4*)w0f;
        #pragma unroll
        for (int i = 0; i < 3; i++) d0[tid + 256 * i] = s0[tid + 256 * i];
        ((uint4*)w1f)[tid] = ((const uint4*)g_w1f)[tid];   // 256 uint4
    }

    // --- block -> (b, ty0, tx0) ---
    int bb = blockIdx.x;
    const int tx0 = (bb % (IMG / TA_W)) * TA_W;  bb /= (IMG / TA_W);
    const int ty0 = (bb % (IMG / TA_H)) * TA_H;  bb /= (IMG / TA_H);
    const int b = bb;
    const float* ximg = x + (size_t)b * IMG * IMG * CH;

    // --- halo tile load (pixel-major q-planes, zero pad) ---
    for (int p = tid; p < HA_PIX; p += TA_THREADS) {
        const int hy = ty0 + (p / HA_W) - 1;
        const int hx = tx0 + (p % HA_W) - 1;
        if ((unsigned)hy < IMG && (unsigned)hx < IMG) {
            const float4* src = (const float4*)(ximg + ((size_t)hy * IMG + hx) * CH);
            #pragma unroll
            for (int q = 0; q < 4; q++)
                *(float4*)(sxp + q * SXQ + p * 4) = src[q];
        } else {
            const float4 z = make_float4(0.f, 0.f, 0.f, 0.f);
            #pragma unroll
            for (int q = 0; q < 4; q++)
                *(float4*)(sxp + q * SXQ + p * 4) = z;
        }
    }
    __syncthreads();

    // --- perceive: 2 threads/pixel, 8 channels each -> 24 features ---
    {
        const int p    = tid >> 1;
        const int half = tid & 1;
        const int pty = p >> 5, ptx = p & 31;
        const int pcen = (pty + 1) * HA_W + (ptx + 1);
        uint32_t* yrow = sY + p * YSTRIDE;

        float feat[24];
        #pragma unroll
        for (int qq = 0; qq < 2; qq++) {
            const int q = 2 * half + qq;
            const float* pl = sxp + q * SXQ;
            const float4 v00 = *(const float4*)(pl + (pcen - HA_W - 1) * 4);
            const float4 v01 = *(const float4*)(pl + (pcen - HA_W    ) * 4);
            const float4 v02 = *(const float4*)(pl + (pcen - HA_W + 1) * 4);
            const float4 v10 = *(const float4*)(pl + (pcen        - 1) * 4);
            const float4 v11 = *(const float4*)(pl + (pcen           ) * 4);
            const float4 v12 = *(const float4*)(pl + (pcen        + 1) * 4);
            const float4 v20 = *(const float4*)(pl + (pcen + HA_W - 1) * 4);
            const float4 v21 = *(const float4*)(pl + (pcen + HA_W    ) * 4);
            const float4 v22 = *(const float4*)(pl + (pcen + HA_W + 1) * 4);

            #define NCA_SOB(MEM, RI)                                                  \
            {                                                                         \
                const int fb = 3 * (4 * qq + RI);                                     \
                feat[fb + 0] = v11.MEM;                                               \
                feat[fb + 1] = ((v02.MEM + v22.MEM) - (v00.MEM + v20.MEM)             \
                                + 2.0f * (v12.MEM - v10.MEM)) * 0.125f;               \
                feat[fb + 2] = ((v20.MEM + v22.MEM) - (v00.MEM + v02.MEM)             \
                                + 2.0f * (v21.MEM - v01.MEM)) * 0.125f;               \
            }
            NCA_SOB(x, 0) NCA_SOB(y, 1) NCA_SOB(z, 2) NCA_SOB(w, 3)
            #undef NCA_SOB
        }
        const int wbase = 12 * half;
        #pragma unroll
        for (int wl = 0; wl < 12; wl++)
            yrow[physw(wbase + wl)] = pk2h(feat[2 * wl], feat[2 * wl + 1]);
    }
    __syncthreads();

    // --- prefetch rmask (broadcast across quads) ---
    const int pty = warp >> 1;
    const int gy  = ty0 + pty;
    const int ptx0 = ((warp & 1) << 4) + gid;
    const size_t pixr0 = ((size_t)b * IMG + gy) * IMG + (tx0 + ptx0);
    const size_t pixr1 = pixr0 + 8;
    const float rm0 = rmask[pixr0];
    const float rm1 = rmask[pixr1];

    // --- A-fragments for GEMM1 ---
    const int pbase = warp * 16;
    uint32_t a1f[3][4];
    #pragma unroll
    for (int s = 0; s < 3; s++) {
        const uint2 lo = *(const uint2*)(sY + (pbase + gid)     * YSTRIDE + 8 * s + 2 * tig);
        const uint2 hi = *(const uint2*)(sY + (pbase + gid + 8) * YSTRIDE + 8 * s + 2 * tig);
        a1f[s][0] = lo.x;  a1f[s][1] = hi.x;
        a1f[s][2] = lo.y;  a1f[s][3] = hi.y;
    }

    // --- fused GEMM1 -> relu/pack -> GEMM2 per 16-wide hidden slice ---
    float d[2][4];
    #pragma unroll
    for (int jj = 0; jj < 2; jj++)
        #pragma unroll
        for (int q = 0; q < 4; q++) d[jj][q] = 0.0f;

    #pragma unroll
    for (int s2 = 0; s2 < 8; s2++) {
        float acc0[4] = {0.f, 0.f, 0.f, 0.f};
        float acc1[4] = {0.f, 0.f, 0.f, 0.f};
        #pragma unroll
        for (int s = 0; s < 3; s++) {
            const uint4 bb4 = ((const uint4*)w0f)[(s * 8 + s2) * 32 + lane];
            mma_f16(acc0, a1f[s][0], a1f[s][1], a1f[s][2], a1f[s][3], bb4.x, bb4.y);
            mma_f16(acc1, a1f[s][0], a1f[s][1], a1f[s][2], a1f[s][3], bb4.z, bb4.w);
        }
        const uint32_t af0 = pk2h(fmaxf(acc0[0], 0.f), fmaxf(acc0[1], 0.f));
        const uint32_t af1 = pk2h(fmaxf(acc0[2], 0.f), fmaxf(acc0[3], 0.f));
        const uint32_t af2 = pk2h(fmaxf(acc1[0], 0.f), fmaxf(acc1[1], 0.f));
        const uint32_t af3 = pk2h(fmaxf(acc1[2], 0.f), fmaxf(acc1[3], 0.f));
        const uint4 b2 = ((const uint4*)w1f)[s2 * 32 + lane];
        mma_f16(d[0], af0, af1, af2, af3, b2.x, b2.y);
        mma_f16(d[1], af0, af1, af2, af3, b2.z, b2.w);
    }

    // --- epilogue: x_new = x + dx*(rand<=0.5) -> OUT directly ---
    #pragma unroll
    for (int rr = 0; rr < 2; rr++) {
        const int r  = gid + 8 * rr;
        const int ptx = ((warp & 1) << 4) + r;
        const int pc = (pty + 1) * HA_W + (ptx + 1);
        const size_t pix = (rr == 0) ? pixr0 : pixr1;
        const float upd = ((rr == 0 ? rm0 : rm1) <= 0.5f) ? 1.0f : 0.0f;
        #pragma unroll
        for (int jj = 0; jj < 2; jj++) {
            const int ch = 8 * jj + 2 * tig;
            const int q = ch >> 2, rm2 = ch & 3;
            const float2 xv = *(const float2*)(sxp + q * SXQ + pc * 4 + rm2);
            float2 v;
            v.x = xv.x + d[jj][2 * rr + 0] * upd;
            v.y = xv.y + d[jj][2 * rr + 1] * upd;
            *(float2*)(out + pix * CH + ch) = v;
            if (jj == 0 && tig == 1) {           // ch pair (2,3): alpha = .y
                g_an[pix] = v.y;
                g_ao[pix] = xv.y;
            }
        }
    }
}

// ------------------------------- Pass B (fix-up) ----------------------------
#define TB_H 8
#define TB_W 32
#define HB_H (TB_H + 2)
#define HB_W (TB_W + 2)
#define TB_THREADS (TB_H * TB_W)   // 256

__global__ __launch_bounds__(TB_THREADS)
void nca_pass_b(float* __restrict__ out)
{
    __shared__ float sao[HB_H * HB_W];
    __shared__ float san[HB_H * HB_W];

    const int tid = threadIdx.x;
    int bb = blockIdx.x;
    const int tx0 = (bb % (IMG / TB_W)) * TB_W;  bb /= (IMG / TB_W);
    const int ty0 = (bb % (IMG / TB_H)) * TB_H;  bb /= (IMG / TB_H);
    const int b = bb;
    const size_t ibase = (size_t)b * IMG * IMG;

    for (int p = tid; p < HB_H * HB_W; p += TB_THREADS) {
        const int hy = ty0 + (p / HB_W) - 1;
        const int hx = tx0 + (p % HB_W) - 1;
        if ((unsigned)hy < IMG && (unsigned)hx < IMG) {
            const size_t pix = ibase + (size_t)hy * IMG + hx;
            sao[p] = g_ao[pix];
            san[p] = g_an[pix];
        } else {
            sao[p] = 0.0f;
            san[p] = 0.0f;
        }
    }
    __syncthreads();

    const int ty = tid / TB_W, tx = tid % TB_W;
    const int pc = (ty + 1) * HB_W + (tx + 1);

    float mo = sao[pc - HB_W - 1];
    mo = fmaxf(mo, sao[pc - HB_W]);     mo = fmaxf(mo, sao[pc - HB_W + 1]);
    mo = fmaxf(mo, sao[pc - 1]);        mo = fmaxf(mo, sao[pc]);
    mo = fmaxf(mo, sao[pc + 1]);        mo = fmaxf(mo, sao[pc + HB_W - 1]);
    mo = fmaxf(mo, sao[pc + HB_W]);     mo = fmaxf(mo, sao[pc + HB_W + 1]);

    float mn = san[pc - HB_W - 1];
    mn = fmaxf(mn, san[pc - HB_W]);     mn = fmaxf(mn, san[pc - HB_W + 1]);
    mn = fmaxf(mn, san[pc - 1]);        mn = fmaxf(mn, san[pc]);
    mn = fmaxf(mn, san[pc + 1]);        mn = fmaxf(mn, san[pc + HB_W - 1]);
    mn = fmaxf(mn, san[pc + HB_W]);     mn = fmaxf(mn, san[pc + HB_W + 1]);

    // out already holds x_new; only dead pixels need zeroing.
    if (!(mo > 0.1f && mn > 0.1f)) {
        const size_t pix = ibase + (size_t)(ty0 + ty) * IMG + (tx0 + tx);
        float4* dst = (float4*)(out + pix * CH);
        const float4 z = make_float4(0.f, 0.f, 0.f, 0.f);
        dst[0] = z; dst[1] = z; dst[2] = z; dst[3] = z;
    }
}

// ----------------------------------------------------------------------------
extern "C" void kernel_launch(void* const* d_in, const int* in_sizes, int n_in,
                              void* d_out, int out_size)
{
    (void)in_sizes; (void)n_in; (void)out_size;
    const float* x  = (const float*)d_in[0];
    const float* w0 = (const float*)d_in[1];
    const float* w1 = (const float*)d_in[2];
    const float* rm = (const float*)d_in[3];
    float* out = (float*)d_out;

    cudaFuncSetAttribute(nca_pass_a, cudaFuncAttributeMaxDynamicSharedMemorySize,
                         SMEM_A_BYTES);

    const int grid_a = BATCH * (IMG / TA_H) * (IMG / TA_W); // 8192
    const int grid_b = BATCH * (IMG / TB_H) * (IMG / TB_W); // 4096

    nca_pack<<<6, 256>>>(w0, w1);
    nca_pass_a<<<grid_a, TA_THREADS, SMEM_A_BYTES>>>(x, rm, out);
    nca_pass_b<<<grid_b, TB_THREADS>>>(out);
}

// round 7
// speedup vs baseline: 5.8405x; 1.0957x over previous
#include <cuda_runtime.h>
#include <cuda_fp16.h>
#include <math.h>
#include <stdint.h>

// ---------------------------------------------------------------------------
// Neural CA step, fp16 mma.sync (m16n8k16), fp32 accumulate.
//   Pass A: 8x32 px tile/block, 32 px/warp (two m16 tiles share B-frags).
//           halo -> perceive (1 px/thread, STS.128 Y writes) ->
//           fused GEMM1(+relu+pack)->GEMM2 -> x_new direct to out.
//   Pass B: fix-up — zero dead pixels per 3x3 alpha maxpool gating.
// ---------------------------------------------------------------------------

#define CH    16
#define NK    48
#define HID   128
#define IMG   256
#define BATCH 16

__device__ float g_an[(size_t)BATCH * IMG * IMG];
__device__ float g_ao[(size_t)BATCH * IMG * IMG];
__device__ uint2 g_w0f[3 * 8 * 32 * 2];   // uint4-pairable GEMM1 B-frags
__device__ uint2 g_w1f[8 * 32 * 2];       // uint4-pairable GEMM2 B-frags

__device__ __forceinline__ uint32_t pk2h(float lo, float hi) {
    __half2 h = __floats2half2_rn(lo, hi);
    return *(uint32_t*)&h;
}

__device__ __forceinline__ void mma_f16(float c[4],
                                        uint32_t a0, uint32_t a1, uint32_t a2, uint32_t a3,
                                        uint32_t b0, uint32_t b1) {
    asm volatile(
        "mma.sync.aligned.m16n8k16.row.col.f32.f16.f16.f32 "
        "{%0,%1,%2,%3}, {%4,%5,%6,%7}, {%8,%9}, {%0,%1,%2,%3};"
        : "+f"(c[0]), "+f"(c[1]), "+f"(c[2]), "+f"(c[3])
        : "r"(a0), "r"(a1), "r"(a2), "r"(a3), "r"(b0), "r"(b1));
}

// ---------------------------- setup: pack weights ---------------------------
__global__ void nca_pack(const float* __restrict__ w0, const float* __restrict__ w1)
{
    const int idx = blockIdx.x * blockDim.x + threadIdx.x;
    if (idx < 3 * 8 * 32 * 2) {
        const int which = idx & 1;
        const int lane  = (idx >> 1) & 31;
        const int s2    = (idx >> 6) & 7;
        const int s     = idx >> 9;
        const int j = 2 * s2 + which;
        const int k = 16 * s + 2 * (lane & 3);
        const int n = 8 * j + (lane >> 2);
        g_w0f[idx] = make_uint2(pk2h(w0[n * NK + k],     w0[n * NK + k + 1]),
                                pk2h(w0[n * NK + k + 8], w0[n * NK + k + 9]));
    }
    if (idx < 8 * 32 * 2) {
        const int jj   = idx & 1;
        const int lane = (idx >> 1) & 31;
        const int s    = idx >> 6;
        const int k = 16 * s + 2 * (lane & 3);
        const int n = 8 * jj + (lane >> 2);
        g_w1f[idx] = make_uint2(pk2h(w1[n * HID + k],     w1[n * HID + k + 1]),
                                pk2h(w1[n * HID + k + 8], w1[n * HID + k + 9]));
    }
}

// ------------------------------- Pass A ------------------------------------
#define TA_H 8
#define TA_W 32
#define HA_H (TA_H + 2)              // 10
#define HA_W (TA_W + 2)              // 34
#define TA_THREADS 256               // 8 warps, 32 pixels each (2 m16 tiles)
#define HA_PIX (HA_H * HA_W)         // 340
#define SXQ (HA_PIX * 4 + 8)         // 1368 words per q-plane
#define YSTRIDE 40                   // u32 words per Y row (24 used + pad)

// smem layout (32-bit words)
#define OFF_SX   0
#define OFF_SY   (OFF_SX + 4 * SXQ)                  // 5472
#define OFF_W0F  (OFF_SY + 256 * YSTRIDE)            // 15712
#define OFF_W1F  (OFF_W0F + 3072)                    // 18784
#define SMEM_A_WORDS (OFF_W1F + 1024)                // 19808
#define SMEM_A_BYTES (SMEM_A_WORDS * 4)              // 79232

__global__ __launch_bounds__(TA_THREADS, 2)
void nca_pass_a(const float* __restrict__ x,
                const float* __restrict__ rmask,
                float* __restrict__ out)
{
    extern __shared__ float smem[];
    float*    sxp = smem + OFF_SX;
    uint32_t* sY  = (uint32_t*)smem + OFF_SY;
    uint32_t* w0f = (uint32_t*)smem + OFF_W0F;
    uint32_t* w1f = (uint32_t*)smem + OFF_W1F;

    const int tid  = threadIdx.x;
    const int lane = tid & 31;
    const int warp = tid >> 5;
    const int tig  = lane & 3;
    const int gid  = lane >> 2;

    // --- weight smem fill (vectorized, pre-packed) ---
    {
        const uint4* s0 = (const uint4*)g_w0f;     // 768 uint4
        uint4* d0 = (uint4*)w0f;
        #pragma unroll
        for (int i = 0; i < 3; i++) d0[tid + 256 * i] = s0[tid + 256 * i];
        ((uint4*)w1f)[tid] = ((const uint4*)g_w1f)[tid];   // 256 uint4
    }

    // --- block -> (b, ty0, tx0) ---
    int bb = blockIdx.x;
    const int tx0 = (bb & 7) * TA_W;   bb >>= 3;     // IMG/TA_W = 8
    const int ty0 = (bb & 31) * TA_H;  bb >>= 5;     // IMG/TA_H = 32
    const int b = bb;
    const float* ximg = x + (size_t)b * IMG * IMG * CH;

    // --- halo tile load (pixel-major q-planes, zero pad) ---
    for (int p = tid; p < HA_PIX; p += TA_THREADS) {
        const int hy = ty0 + (p / HA_W) - 1;
        const int hx = tx0 + (p % HA_W) - 1;
        if ((unsigned)hy < IMG && (unsigned)hx < IMG) {
            const float4* src = (const float4*)(ximg + ((size_t)hy * IMG + hx) * CH);
            #pragma unroll
            for (int q = 0; q < 4; q++)
                *(float4*)(sxp + q * SXQ + p * 4) = src[q];
        } else {
            const float4 z = make_float4(0.f, 0.f, 0.f, 0.f);
            #pragma unroll
            for (int q = 0; q < 4; q++)
                *(float4*)(sxp + q * SXQ + p * 4) = z;
        }
    }
    __syncthreads();

    // --- perceive: 1 thread = 1 pixel, all 16 channels -> 48 features ---
    {
        const int pty = tid >> 5, ptx = tid & 31;   // warp row, lane col
        const int pcen = (pty + 1) * HA_W + (ptx + 1);

        float feat[48];
        #pragma unroll
        for (int q = 0; q < 4; q++) {
            const float* pl = sxp + q * SXQ;
            const float4 v00 = *(const float4*)(pl + (pcen - HA_W - 1) * 4);
            const float4 v01 = *(const float4*)(pl + (pcen - HA_W    ) * 4);
            const float4 v02 = *(const float4*)(pl + (pcen - HA_W + 1) * 4);
            const float4 v10 = *(const float4*)(pl + (pcen        - 1) * 4);
            const float4 v11 = *(const float4*)(pl + (pcen           ) * 4);
            const float4 v12 = *(const float4*)(pl + (pcen        + 1) * 4);
            const float4 v20 = *(const float4*)(pl + (pcen + HA_W - 1) * 4);
            const float4 v21 = *(const float4*)(pl + (pcen + HA_W    ) * 4);
            const float4 v22 = *(const float4*)(pl + (pcen + HA_W + 1) * 4);

            #define NCA_SOB(MEM, RI)                                                  \
            {                                                                         \
                const int fb = 12 * q + 3 * RI;                                       \
                feat[fb + 0] = v11.MEM;                                               \
                feat[fb + 1] = ((v02.MEM + v22.MEM) - (v00.MEM + v20.MEM)             \
                                + 2.0f * (v12.MEM - v10.MEM)) * 0.125f;               \
                feat[fb + 2] = ((v20.MEM + v22.MEM) - (v00.MEM + v02.MEM)             \
                                + 2.0f * (v21.MEM - v01.MEM)) * 0.125f;               \
            }
            NCA_SOB(x, 0) NCA_SOB(y, 1) NCA_SOB(z, 2) NCA_SOB(w, 3)
            #undef NCA_SOB
        }

        // pack + STS.128: physical word 8s+4u+{0..3} = features
        // (16s+4u,+1), (16s+4u+8,+9), (16s+4u+2,+3), (16s+4u+10,+11)
        uint32_t* yrow = sY + tid * YSTRIDE;
        #pragma unroll
        for (int s = 0; s < 3; s++) {
            #pragma unroll
            for (int u = 0; u < 2; u++) {
                const int fb = 16 * s + 4 * u;
                uint4 wv;
                wv.x = pk2h(feat[fb + 0],  feat[fb + 1]);
                wv.y = pk2h(feat[fb + 8],  feat[fb + 9]);
                wv.z = pk2h(feat[fb + 2],  feat[fb + 3]);
                wv.w = pk2h(feat[fb + 10], feat[fb + 11]);
                *(uint4*)(yrow + 8 * s + 4 * u) = wv;
            }
        }
    }
    __syncthreads();

    // --- prefetch rmask (4 pixels per thread: 2 tiles x 2 rows) ---
    const int gy = ty0 + warp;
    const size_t rowbase = ((size_t)b * IMG + gy) * IMG + tx0;
    size_t pixp[2][2];
    float rmv[2][2];
    #pragma unroll
    for (int tt = 0; tt < 2; tt++)
        #pragma unroll
        for (int rr = 0; rr < 2; rr++) {
            pixp[tt][rr] = rowbase + 16 * tt + gid + 8 * rr;
            rmv[tt][rr] = rmask[pixp[tt][rr]];
        }

    // --- A-fragments for both m16 tiles ---
    uint32_t a1f[2][3][4];
    #pragma unroll
    for (int tt = 0; tt < 2; tt++) {
        const int rb = warp * 32 + 16 * tt;
        #pragma unroll
        for (int s = 0; s < 3; s++) {
            const uint2 lo = *(const uint2*)(sY + (rb + gid)     * YSTRIDE + 8 * s + 2 * tig);
            const uint2 hi = *(const uint2*)(sY + (rb + gid + 8) * YSTRIDE + 8 * s + 2 * tig);
            a1f[tt][s][0] = lo.x;  a1f[tt][s][1] = hi.x;
            a1f[tt][s][2] = lo.y;  a1f[tt][s][3] = hi.y;
        }
    }

    // --- fused GEMM1 -> relu/pack -> GEMM2, B-frags shared by both tiles ---
    float d[2][2][4];
    #pragma unroll
    for (int tt = 0; tt < 2; tt++)
        #pragma unroll
        for (int jj = 0; jj < 2; jj++)
            #pragma unroll
            for (int q = 0; q < 4; q++) d[tt][jj][q] = 0.0f;

    #pragma unroll
    for (int s2 = 0; s2 < 8; s2++) {
        float aA0[4] = {0.f,0.f,0.f,0.f}, aA1[4] = {0.f,0.f,0.f,0.f};
        float aB0[4] = {0.f,0.f,0.f,0.f}, aB1[4] = {0.f,0.f,0.f,0.f};
        #pragma unroll
        for (int s = 0; s < 3; s++) {
            const uint4 bb4 = ((const uint4*)w0f)[(s * 8 + s2) * 32 + lane];
            mma_f16(aA0, a1f[0][s][0], a1f[0][s][1], a1f[0][s][2], a1f[0][s][3], bb4.x, bb4.y);
            mma_f16(aA1, a1f[0][s][0], a1f[0][s][1], a1f[0][s][2], a1f[0][s][3], bb4.z, bb4.w);
            mma_f16(aB0, a1f[1][s][0], a1f[1][s][1], a1f[1][s][2], a1f[1][s][3], bb4.x, bb4.y);
            mma_f16(aB1, a1f[1][s][0], a1f[1][s][1], a1f[1][s][2], a1f[1][s][3], bb4.z, bb4.w);
        }
        const uint4 b2 = ((const uint4*)w1f)[s2 * 32 + lane];
        {
            const uint32_t f0 = pk2h(fmaxf(aA0[0], 0.f), fmaxf(aA0[1], 0.f));
            const uint32_t f1 = pk2h(fmaxf(aA0[2], 0.f), fmaxf(aA0[3], 0.f));
            const uint32_t f2 = pk2h(fmaxf(aA1[0], 0.f), fmaxf(aA1[1], 0.f));
            const uint32_t f3 = pk2h(fmaxf(aA1[2], 0.f), fmaxf(aA1[3], 0.f));
            mma_f16(d[0][0], f0, f1, f2, f3, b2.x, b2.y);
            mma_f16(d[0][1], f0, f1, f2, f3, b2.z, b2.w);
        }
        {
            const uint32_t f0 = pk2h(fmaxf(aB0[0], 0.f), fmaxf(aB0[1], 0.f));
            const uint32_t f1 = pk2h(fmaxf(aB0[2], 0.f), fmaxf(aB0[3], 0.f));
            const uint32_t f2 = pk2h(fmaxf(aB1[0], 0.f), fmaxf(aB1[1], 0.f));
            const uint32_t f3 = pk2h(fmaxf(aB1[2], 0.f), fmaxf(aB1[3], 0.f));
            mma_f16(d[1][0], f0, f1, f2, f3, b2.x, b2.y);
            mma_f16(d[1][1], f0, f1, f2, f3, b2.z, b2.w);
        }
    }

    // --- epilogue: x_new = x + dx*(rand<=0.5) -> OUT directly ---
    #pragma unroll
    for (int tt = 0; tt < 2; tt++) {
        #pragma unroll
        for (int rr = 0; rr < 2; rr++) {
            const int ptx = 16 * tt + gid + 8 * rr;
            const int pc = (warp + 1) * HA_W + (ptx + 1);
            const size_t pix = pixp[tt][rr];
            const float upd = (rmv[tt][rr] <= 0.5f) ? 1.0f : 0.0f;
            #pragma unroll
            for (int jj = 0; jj < 2; jj++) {
                const int ch = 8 * jj + 2 * tig;
                const int q = ch >> 2, rm2 = ch & 3;
                const float2 xv = *(const float2*)(sxp + q * SXQ + pc * 4 + rm2);
                float2 v;
                v.x = xv.x + d[tt][jj][2 * rr + 0] * upd;
                v.y = xv.y + d[tt][jj][2 * rr + 1] * upd;
                *(float2*)(out + pix * CH + ch) = v;
                if (jj == 0 && tig == 1) {       // ch pair (2,3): alpha = .y
                    g_an[pix] = v.y;
                    g_ao[pix] = xv.y;
                }
            }
        }
    }
}

// ------------------------------- Pass B (fix-up) ----------------------------
#define TB_H 8
#define TB_W 32
#define HB_H (TB_H + 2)
#define HB_W (TB_W + 2)
#define TB_THREADS (TB_H * TB_W)   // 256

__global__ __launch_bounds__(TB_THREADS)
void nca_pass_b(float* __restrict__ out)
{
    __shared__ float sao[HB_H * HB_W];
    __shared__ float san[HB_H * HB_W];

    const int tid = threadIdx.x;
    int bb = blockIdx.x;
    const int tx0 = (bb % (IMG / TB_W)) * TB_W;  bb /= (IMG / TB_W);
    const int ty0 = (bb % (IMG / TB_H)) * TB_H;  bb /= (IMG / TB_H);
    const int b = bb;
    const size_t ibase = (size_t)b * IMG * IMG;

    for (int p = tid; p < HB_H * HB_W; p += TB_THREADS) {
        const int hy = ty0 + (p / HB_W) - 1;
        const int hx = tx0 + (p % HB_W) - 1;
        if ((unsigned)hy < IMG && (unsigned)hx < IMG) {
            const size_t pix = ibase + (size_t)hy * IMG + hx;
            sao[p] = g_ao[pix];
            san[p] = g_an[pix];
        } else {
            sao[p] = 0.0f;
            san[p] = 0.0f;
        }
    }
    __syncthreads();

    const int ty = tid / TB_W, tx = tid % TB_W;
    const int pc = (ty + 1) * HB_W + (tx + 1);

    float mo = sao[pc - HB_W - 1];
    mo = fmaxf(mo, sao[pc - HB_W]);     mo = fmaxf(mo, sao[pc - HB_W + 1]);
    mo = fmaxf(mo, sao[pc - 1]);        mo = fmaxf(mo, sao[pc]);
    mo = fmaxf(mo, sao[pc + 1]);        mo = fmaxf(mo, sao[pc + HB_W - 1]);
    mo = fmaxf(mo, sao[pc + HB_W]);     mo = fmaxf(mo, sao[pc + HB_W + 1]);

    float mn = san[pc - HB_W - 1];
    mn = fmaxf(mn, san[pc - HB_W]);     mn = fmaxf(mn, san[pc - HB_W + 1]);
    mn = fmaxf(mn, san[pc - 1]);        mn = fmaxf(mn, san[pc]);
    mn = fmaxf(mn, san[pc + 1]);        mn = fmaxf(mn, san[pc + HB_W - 1]);
    mn = fmaxf(mn, san[pc + HB_W]);     mn = fmaxf(mn, san[pc + HB_W + 1]);

    // out already holds x_new; only dead pixels need zeroing.
    if (!(mo > 0.1f && mn > 0.1f)) {
        const size_t pix = ibase + (size_t)(ty0 + ty) * IMG + (tx0 + tx);
        float4* dst = (float4*)(out + pix * CH);
        const float4 z = make_float4(0.f, 0.f, 0.f, 0.f);
        dst[0] = z; dst[1] = z; dst[2] = z; dst[3] = z;
    }
}

// ----------------------------------------------------------------------------
extern "C" void kernel_launch(void* const* d_in, const int* in_sizes, int n_in,
                              void* d_out, int out_size)
{
    (void)in_sizes; (void)n_in; (void)out_size;
    const float* x  = (const float*)d_in[0];
    const float* w0 = (const float*)d_in[1];
    const float* w1 = (const float*)d_in[2];
    const float* rm = (const float*)d_in[3];
    float* out = (float*)d_out;

    cudaFuncSetAttribute(nca_pass_a, cudaFuncAttributeMaxDynamicSharedMemorySize,
                         SMEM_A_BYTES);

    const int grid_a = BATCH * (IMG / TA_H) * (IMG / TA_W); // 4096
    const int grid_b = BATCH * (IMG / TB_H) * (IMG / TB_W); // 4096

    nca_pack<<<6, 256>>>(w0, w1);
    nca_pass_a<<<grid_a, TA_THREADS, SMEM_A_BYTES>>>(x, rm, out);
    nca_pass_b<<<grid_b, TB_THREADS>>>(out);
}

// round 8
// speedup vs baseline: 6.4203x; 1.0993x over previous
#include <cuda_runtime.h>
#include <cuda_fp16.h>
#include <math.h>
#include <stdint.h>

// ---------------------------------------------------------------------------
// Neural CA step, fp16 mma.sync (m16n8k16), fp32 accumulate.
//   Pass A: 8x32 px tile/block, 32 px/warp (two m16 tiles share B-frags),
//           occupancy 3 (smem 62.8KB, YSTRIDE 24). x_new direct to out.
//   Pass B: fix-up — zero dead pixels; alpha planes packed as float2.
// ---------------------------------------------------------------------------

#define CH    16
#define NK    48
#define HID   128
#define IMG   256
#define BATCH 16

__device__ float2 g_aon[(size_t)BATCH * IMG * IMG];   // (alpha_old, alpha_new)
__device__ uint2 g_w0f[3 * 8 * 32 * 2];   // uint4-pairable GEMM1 B-frags
__device__ uint2 g_w1f[8 * 32 * 2];       // uint4-pairable GEMM2 B-frags

__device__ __forceinline__ uint32_t pk2h(float lo, float hi) {
    __half2 h = __floats2half2_rn(lo, hi);
    return *(uint32_t*)&h;
}

__device__ __forceinline__ void mma_f16(float c[4],
                                        uint32_t a0, uint32_t a1, uint32_t a2, uint32_t a3,
                                        uint32_t b0, uint32_t b1) {
    asm volatile(
        "mma.sync.aligned.m16n8k16.row.col.f32.f16.f16.f32 "
        "{%0,%1,%2,%3}, {%4,%5,%6,%7}, {%8,%9}, {%0,%1,%2,%3};"
        : "+f"(c[0]), "+f"(c[1]), "+f"(c[2]), "+f"(c[3])
        : "r"(a0), "r"(a1), "r"(a2), "r"(a3), "r"(b0), "r"(b1));
}

// ---------------------------- setup: pack weights ---------------------------
__global__ void nca_pack(const float* __restrict__ w0, const float* __restrict__ w1)
{
    const int idx = blockIdx.x * blockDim.x + threadIdx.x;
    if (idx < 3 * 8 * 32 * 2) {
        const int which = idx & 1;
        const int lane  = (idx >> 1) & 31;
        const int s2    = (idx >> 6) & 7;
        const int s     = idx >> 9;
        const int j = 2 * s2 + which;
        const int k = 16 * s + 2 * (lane & 3);
        const int n = 8 * j + (lane >> 2);
        g_w0f[idx] = make_uint2(pk2h(w0[n * NK + k],     w0[n * NK + k + 1]),
                                pk2h(w0[n * NK + k + 8], w0[n * NK + k + 9]));
    }
    if (idx < 8 * 32 * 2) {
        const int jj   = idx & 1;
        const int lane = (idx >> 1) & 31;
        const int s    = idx >> 6;
        const int k = 16 * s + 2 * (lane & 3);
        const int n = 8 * jj + (lane >> 2);
        g_w1f[idx] = make_uint2(pk2h(w1[n * HID + k],     w1[n * HID + k + 1]),
                                pk2h(w1[n * HID + k + 8], w1[n * HID + k + 9]));
    }
}

// ------------------------------- Pass A ------------------------------------
#define TA_H 8
#define TA_W 32
#define HA_H (TA_H + 2)              // 10
#define HA_W (TA_W + 2)              // 34
#define TA_THREADS 256               // 8 warps, 32 pixels each (2 m16 tiles)
#define HA_PIX (HA_H * HA_W)         // 340
#define SXQ (HA_PIX * 4 + 8)         // 1368 words per q-plane
#define YSTRIDE 24                   // u32 words per Y row (24 used, no pad)

// smem layout (32-bit words)
#define OFF_SX   0
#define OFF_SY   (OFF_SX + 4 * SXQ)                  // 5472
#define OFF_W0F  (OFF_SY + 256 * YSTRIDE)            // 11616
#define OFF_W1F  (OFF_W0F + 3072)                    // 14688
#define SMEM_A_WORDS (OFF_W1F + 1024)                // 15712
#define SMEM_A_BYTES (SMEM_A_WORDS * 4)              // 62848

__global__ __launch_bounds__(TA_THREADS, 3)
void nca_pass_a(const float* __restrict__ x,
                const float* __restrict__ rmask,
                float* __restrict__ out)
{
    extern __shared__ float smem[];
    float*    sxp = smem + OFF_SX;
    uint32_t* sY  = (uint32_t*)smem + OFF_SY;
    uint32_t* w0f = (uint32_t*)smem + OFF_W0F;
    uint32_t* w1f = (uint32_t*)smem + OFF_W1F;

    const int tid  = threadIdx.x;
    const int lane = tid & 31;
    const int warp = tid >> 5;
    const int tig  = lane & 3;
    const int gid  = lane >> 2;

    // --- weight smem fill (vectorized, pre-packed) ---
    {
        const uint4* s0 = (const uint4*)g_w0f;     // 768 uint4
        uint4* d0 = (uint4*)w0f;
        #pragma unroll
        for (int i = 0; i < 3; i++) d0[tid + 256 * i] = s0[tid + 256 * i];
        ((uint4*)w1f)[tid] = ((const uint4*)g_w1f)[tid];   // 256 uint4
    }

    // --- block -> (b, ty0, tx0) ---
    int bb = blockIdx.x;
    const int tx0 = (bb & 7) * TA_W;   bb >>= 3;     // IMG/TA_W = 8
    const int ty0 = (bb & 31) * TA_H;  bb >>= 5;     // IMG/TA_H = 32
    const int b = bb;
    const float* ximg = x + (size_t)b * IMG * IMG * CH;

    // --- halo tile load (pixel-major q-planes, zero pad) ---
    for (int p = tid; p < HA_PIX; p += TA_THREADS) {
        const int hy = ty0 + (p / HA_W) - 1;
        const int hx = tx0 + (p % HA_W) - 1;
        if ((unsigned)hy < IMG && (unsigned)hx < IMG) {
            const float4* src = (const float4*)(ximg + ((size_t)hy * IMG + hx) * CH);
            #pragma unroll
            for (int q = 0; q < 4; q++)
                *(float4*)(sxp + q * SXQ + p * 4) = src[q];
        } else {
            const float4 z = make_float4(0.f, 0.f, 0.f, 0.f);
            #pragma unroll
            for (int q = 0; q < 4; q++)
                *(float4*)(sxp + q * SXQ + p * 4) = z;
        }
    }
    __syncthreads();

    // --- perceive: 1 thread = 1 pixel, all 16 channels -> 48 features ---
    {
        const int pty = tid >> 5, ptx = tid & 31;
        const int pcen = (pty + 1) * HA_W + (ptx + 1);

        float feat[48];
        #pragma unroll
        for (int q = 0; q < 4; q++) {
            const float* pl = sxp + q * SXQ;
            const float4 v00 = *(const float4*)(pl + (pcen - HA_W - 1) * 4);
            const float4 v01 = *(const float4*)(pl + (pcen - HA_W    ) * 4);
            const float4 v02 = *(const float4*)(pl + (pcen - HA_W + 1) * 4);
            const float4 v10 = *(const float4*)(pl + (pcen        - 1) * 4);
            const float4 v11 = *(const float4*)(pl + (pcen           ) * 4);
            const float4 v12 = *(const float4*)(pl + (pcen        + 1) * 4);
            const float4 v20 = *(const float4*)(pl + (pcen + HA_W - 1) * 4);
            const float4 v21 = *(const float4*)(pl + (pcen + HA_W    ) * 4);
            const float4 v22 = *(const float4*)(pl + (pcen + HA_W + 1) * 4);

            #define NCA_SOB(MEM, RI)                                                  \
            {                                                                         \
                const int fb = 12 * q + 3 * RI;                                       \
                feat[fb + 0] = v11.MEM;                                               \
                feat[fb + 1] = ((v02.MEM + v22.MEM) - (v00.MEM + v20.MEM)             \
                                + 2.0f * (v12.MEM - v10.MEM)) * 0.125f;               \
                feat[fb + 2] = ((v20.MEM + v22.MEM) - (v00.MEM + v02.MEM)             \
                                + 2.0f * (v21.MEM - v01.MEM)) * 0.125f;               \
            }
            NCA_SOB(x, 0) NCA_SOB(y, 1) NCA_SOB(z, 2) NCA_SOB(w, 3)
            #undef NCA_SOB
        }

        uint32_t* yrow = sY + tid * YSTRIDE;
        #pragma unroll
        for (int s = 0; s < 3; s++) {
            #pragma unroll
            for (int u = 0; u < 2; u++) {
                const int fb = 16 * s + 4 * u;
                uint4 wv;
                wv.x = pk2h(feat[fb + 0],  feat[fb + 1]);
                wv.y = pk2h(feat[fb + 8],  feat[fb + 9]);
                wv.z = pk2h(feat[fb + 2],  feat[fb + 3]);
                wv.w = pk2h(feat[fb + 10], feat[fb + 11]);
                *(uint4*)(yrow + 8 * s + 4 * u) = wv;
            }
        }
    }
    __syncthreads();

    // --- prefetch rmask (4 pixels per thread: 2 tiles x 2 rows) ---
    const int gy = ty0 + warp;
    const size_t rowbase = ((size_t)b * IMG + gy) * IMG + tx0;
    float rmv[2][2];
    #pragma unroll
    for (int tt = 0; tt < 2; tt++)
        #pragma unroll
        for (int rr = 0; rr < 2; rr++)
            rmv[tt][rr] = rmask[rowbase + 16 * tt + gid + 8 * rr];

    // --- A-fragments for both m16 tiles ---
    uint32_t a1f[2][3][4];
    #pragma unroll
    for (int tt = 0; tt < 2; tt++) {
        const int rb = warp * 32 + 16 * tt;
        #pragma unroll
        for (int s = 0; s < 3; s++) {
            const uint2 lo = *(const uint2*)(sY + (rb + gid)     * YSTRIDE + 8 * s + 2 * tig);
            const uint2 hi = *(const uint2*)(sY + (rb + gid + 8) * YSTRIDE + 8 * s + 2 * tig);
            a1f[tt][s][0] = lo.x;  a1f[tt][s][1] = hi.x;
            a1f[tt][s][2] = lo.y;  a1f[tt][s][3] = hi.y;
        }
    }

    // --- fused GEMM1 -> relu/pack -> GEMM2, B-frags shared by both tiles ---
    float d[2][2][4];
    #pragma unroll
    for (int tt = 0; tt < 2; tt++)
        #pragma unroll
        for (int jj = 0; jj < 2; jj++)
            #pragma unroll
            for (int q = 0; q < 4; q++) d[tt][jj][q] = 0.0f;

    #pragma unroll
    for (int s2 = 0; s2 < 8; s2++) {
        float aA0[4] = {0.f,0.f,0.f,0.f}, aA1[4] = {0.f,0.f,0.f,0.f};
        float aB0[4] = {0.f,0.f,0.f,0.f}, aB1[4] = {0.f,0.f,0.f,0.f};
        #pragma unroll
        for (int s = 0; s < 3; s++) {
            const uint4 bb4 = ((const uint4*)w0f)[(s * 8 + s2) * 32 + lane];
            mma_f16(aA0, a1f[0][s][0], a1f[0][s][1], a1f[0][s][2], a1f[0][s][3], bb4.x, bb4.y);
            mma_f16(aA1, a1f[0][s][0], a1f[0][s][1], a1f[0][s][2], a1f[0][s][3], bb4.z, bb4.w);
            mma_f16(aB0, a1f[1][s][0], a1f[1][s][1], a1f[1][s][2], a1f[1][s][3], bb4.x, bb4.y);
            mma_f16(aB1, a1f[1][s][0], a1f[1][s][1], a1f[1][s][2], a1f[1][s][3], bb4.z, bb4.w);
        }
        const uint4 b2 = ((const uint4*)w1f)[s2 * 32 + lane];
        {
            const uint32_t f0 = pk2h(fmaxf(aA0[0], 0.f), fmaxf(aA0[1], 0.f));
            const uint32_t f1 = pk2h(fmaxf(aA0[2], 0.f), fmaxf(aA0[3], 0.f));
            const uint32_t f2 = pk2h(fmaxf(aA1[0], 0.f), fmaxf(aA1[1], 0.f));
            const uint32_t f3 = pk2h(fmaxf(aA1[2], 0.f), fmaxf(aA1[3], 0.f));
            mma_f16(d[0][0], f0, f1, f2, f3, b2.x, b2.y);
            mma_f16(d[0][1], f0, f1, f2, f3, b2.z, b2.w);
        }
        {
            const uint32_t f0 = pk2h(fmaxf(aB0[0], 0.f), fmaxf(aB0[1], 0.f));
            const uint32_t f1 = pk2h(fmaxf(aB0[2], 0.f), fmaxf(aB0[3], 0.f));
            const uint32_t f2 = pk2h(fmaxf(aB1[0], 0.f), fmaxf(aB1[1], 0.f));
            const uint32_t f3 = pk2h(fmaxf(aB1[2], 0.f), fmaxf(aB1[3], 0.f));
            mma_f16(d[1][0], f0, f1, f2, f3, b2.x, b2.y);
            mma_f16(d[1][1], f0, f1, f2, f3, b2.z, b2.w);
        }
    }

    // --- epilogue: x_new = x + dx*(rand<=0.5) -> OUT directly ---
    #pragma unroll
    for (int tt = 0; tt < 2; tt++) {
        #pragma unroll
        for (int rr = 0; rr < 2; rr++) {
            const int ptx = 16 * tt + gid + 8 * rr;
            const int pc = (warp + 1) * HA_W + (ptx + 1);
            const size_t pix = rowbase + ptx;
            const float upd = (rmv[tt][rr] <= 0.5f) ? 1.0f : 0.0f;
            #pragma unroll
            for (int jj = 0; jj < 2; jj++) {
                const int ch = 8 * jj + 2 * tig;
                const int q = ch >> 2, rm2 = ch & 3;
                const float2 xv = *(const float2*)(sxp + q * SXQ + pc * 4 + rm2);
                float2 v;
                v.x = xv.x + d[tt][jj][2 * rr + 0] * upd;
                v.y = xv.y + d[tt][jj][2 * rr + 1] * upd;
                *(float2*)(out + pix * CH + ch) = v;
                if (jj == 0 && tig == 1) {       // ch pair (2,3): alpha = .y
                    g_aon[pix] = make_float2(xv.y, v.y);   // (old, new)
                }
            }
        }
    }
}

// ------------------------------- Pass B (fix-up) ----------------------------
#define TB_H 8
#define TB_W 32
#define HB_H (TB_H + 2)
#define HB_W (TB_W + 2)
#define TB_THREADS (TB_H * TB_W)   // 256

__global__ __launch_bounds__(TB_THREADS)
void nca_pass_b(float* __restrict__ out)
{
    __shared__ float2 saon[HB_H * HB_W];

    const int tid = threadIdx.x;
    int bb = blockIdx.x;
    const int tx0 = (bb % (IMG / TB_W)) * TB_W;  bb /= (IMG / TB_W);
    const int ty0 = (bb % (IMG / TB_H)) * TB_H;  bb /= (IMG / TB_H);
    const int b = bb;
    const size_t ibase = (size_t)b * IMG * IMG;

    for (int p = tid; p < HB_H * HB_W; p += TB_THREADS) {
        const int hy = ty0 + (p / HB_W) - 1;
        const int hx = tx0 + (p % HB_W) - 1;
        saon[p] = ((unsigned)hy < IMG && (unsigned)hx < IMG)
                    ? g_aon[ibase + (size_t)hy * IMG + hx]
                    : make_float2(0.f, 0.f);
    }
    __syncthreads();

    const int ty = tid / TB_W, tx = tid % TB_W;
    const int pc = (ty + 1) * HB_W + (tx + 1);

    float mo, mn;
    {
        float2 m = saon[pc - HB_W - 1];
        #define NCA_MX(OFF) { float2 t = saon[pc + (OFF)]; \
                              m.x = fmaxf(m.x, t.x); m.y = fmaxf(m.y, t.y); }
        NCA_MX(-HB_W) NCA_MX(-HB_W + 1)
        NCA_MX(-1)    NCA_MX(0)    NCA_MX(1)
        NCA_MX(HB_W - 1) NCA_MX(HB_W) NCA_MX(HB_W + 1)
        #undef NCA_MX
        mo = m.x; mn = m.y;
    }

    // out already holds x_new; only dead pixels need zeroing.
    if (!(mo > 0.1f && mn > 0.1f)) {
        const size_t pix = ibase + (size_t)(ty0 + ty) * IMG + (tx0 + tx);
        float4* dst = (float4*)(out + pix * CH);
        const float4 z = make_float4(0.f, 0.f, 0.f, 0.f);
        dst[0] = z; dst[1] = z; dst[2] = z; dst[3] = z;
    }
}

// ----------------------------------------------------------------------------
extern "C" void kernel_launch(void* const* d_in, const int* in_sizes, int n_in,
                              void* d_out, int out_size)
{
    (void)in_sizes; (void)n_in; (void)out_size;
    const float* x  = (const float*)d_in[0];
    const float* w0 = (const float*)d_in[1];
    const float* w1 = (const float*)d_in[2];
    const float* rm = (const float*)d_in[3];
    float* out = (float*)d_out;

    cudaFuncSetAttribute(nca_pass_a, cudaFuncAttributeMaxDynamicSharedMemorySize,
                         SMEM_A_BYTES);

    const int grid_a = BATCH * (IMG / TA_H) * (IMG / TA_W); // 4096
    const int grid_b = BATCH * (IMG / TB_H) * (IMG / TB_W); // 4096

    nca_pack<<<6, 256>>>(w0, w1);
    nca_pass_a<<<grid_a, TA_THREADS, SMEM_A_BYTES>>>(x, rm, out);
    nca_pass_b<<<grid_b, TB_THREADS>>>(out);
}

// round 9
// speedup vs baseline: 7.1611x; 1.1154x over previous
#include <cuda_runtime.h>
#include <cuda_fp16.h>
#include <math.h>
#include <stdint.h>

// ---------------------------------------------------------------------------
// Neural CA step, fp16 mma.sync (m16n8k16), fp32 accumulate.
//   Pass A: 8x32 px tile/block, 32 px/warp (two m16 tiles share B-frags),
//           occupancy 3. Halo via cp.async; warp-local Y handoff (syncwarp).
//   Pass B: fix-up — zero dead pixels; alpha planes packed as float2.
// ---------------------------------------------------------------------------

#define CH    16
#define NK    48
#define HID   128
#define IMG   256
#define BATCH 16

__device__ float2 g_aon[(size_t)BATCH * IMG * IMG];   // (alpha_old, alpha_new)
__device__ uint2 g_w0f[3 * 8 * 32 * 2];   // uint4-pairable GEMM1 B-frags
__device__ uint2 g_w1f[8 * 32 * 2];       // uint4-pairable GEMM2 B-frags

__device__ __forceinline__ uint32_t pk2h(float lo, float hi) {
    __half2 h = __floats2half2_rn(lo, hi);
    return *(uint32_t*)&h;
}

__device__ __forceinline__ void mma_f16(float c[4],
                                        uint32_t a0, uint32_t a1, uint32_t a2, uint32_t a3,
                                        uint32_t b0, uint32_t b1) {
    asm volatile(
        "mma.sync.aligned.m16n8k16.row.col.f32.f16.f16.f32 "
        "{%0,%1,%2,%3}, {%4,%5,%6,%7}, {%8,%9}, {%0,%1,%2,%3};"
        : "+f"(c[0]), "+f"(c[1]), "+f"(c[2]), "+f"(c[3])
        : "r"(a0), "r"(a1), "r"(a2), "r"(a3), "r"(b0), "r"(b1));
}

__device__ __forceinline__ void cp_async16(uint32_t saddr, const void* gptr) {
    asm volatile("cp.async.cg.shared.global [%0], [%1], 16;"
                 :: "r"(saddr), "l"(gptr));
}

// ---------------------------- setup: pack weights ---------------------------
__global__ void nca_pack(const float* __restrict__ w0, const float* __restrict__ w1)
{
    const int idx = blockIdx.x * blockDim.x + threadIdx.x;
    if (idx < 3 * 8 * 32 * 2) {
        const int which = idx & 1;
        const int lane  = (idx >> 1) & 31;
        const int s2    = (idx >> 6) & 7;
        const int s     = idx >> 9;
        const int j = 2 * s2 + which;
        const int k = 16 * s + 2 * (lane & 3);
        const int n = 8 * j + (lane >> 2);
        g_w0f[idx] = make_uint2(pk2h(w0[n * NK + k],     w0[n * NK + k + 1]),
                                pk2h(w0[n * NK + k + 8], w0[n * NK + k + 9]));
    }
    if (idx < 8 * 32 * 2) {
        const int jj   = idx & 1;
        const int lane = (idx >> 1) & 31;
        const int s    = idx >> 6;
        const int k = 16 * s + 2 * (lane & 3);
        const int n = 8 * jj + (lane >> 2);
        g_w1f[idx] = make_uint2(pk2h(w1[n * HID + k],     w1[n * HID + k + 1]),
                                pk2h(w1[n * HID + k + 8], w1[n * HID + k + 9]));
    }
}

// ------------------------------- Pass A ------------------------------------
#define TA_H 8
#define TA_W 32
#define HA_H (TA_H + 2)              // 10
#define HA_W (TA_W + 2)              // 34
#define TA_THREADS 256               // 8 warps, 32 pixels each (2 m16 tiles)
#define HA_PIX (HA_H * HA_W)         // 340
#define SXQ (HA_PIX * 4 + 8)         // 1368 words per q-plane
#define YSTRIDE 24                   // u32 words per Y row

// smem layout (32-bit words)
#define OFF_SX   0
#define OFF_SY   (OFF_SX + 4 * SXQ)                  // 5472
#define OFF_W0F  (OFF_SY + 256 * YSTRIDE)            // 11616
#define OFF_W1F  (OFF_W0F + 3072)                    // 14688
#define SMEM_A_WORDS (OFF_W1F + 1024)                // 15712
#define SMEM_A_BYTES (SMEM_A_WORDS * 4)              // 62848

__global__ __launch_bounds__(TA_THREADS, 3)
void nca_pass_a(const float* __restrict__ x,
                const float* __restrict__ rmask,
                float* __restrict__ out)
{
    extern __shared__ float smem[];
    float*    sxp = smem + OFF_SX;
    uint32_t* sY  = (uint32_t*)smem + OFF_SY;
    uint32_t* w0f = (uint32_t*)smem + OFF_W0F;
    uint32_t* w1f = (uint32_t*)smem + OFF_W1F;

    const int tid  = threadIdx.x;
    const int lane = tid & 31;
    const int warp = tid >> 5;
    const int tig  = lane & 3;
    const int gid  = lane >> 2;

    const uint32_t smem_base = (uint32_t)__cvta_generic_to_shared(smem);

    // --- weight smem fill via cp.async (pre-packed, coalesced) ---
    {
        const uint32_t dst0 = smem_base + OFF_W0F * 4;
        #pragma unroll
        for (int i = 0; i < 3; i++)
            cp_async16(dst0 + (tid + 256 * i) * 16, (const char*)g_w0f + (tid + 256 * i) * 16);
        cp_async16(smem_base + OFF_W1F * 4 + tid * 16, (const char*)g_w1f + tid * 16);
    }

    // --- block -> (b, ty0, tx0) ---
    int bb = blockIdx.x;
    const int tx0 = (bb & 7) * TA_W;   bb >>= 3;     // IMG/TA_W = 8
    const int ty0 = (bb & 31) * TA_H;  bb >>= 5;     // IMG/TA_H = 32
    const int b = bb;
    const float* ximg = x + (size_t)b * IMG * IMG * CH;

    // --- halo tile fill via cp.async (zero OOB via STS) ---
    for (int p = tid; p < HA_PIX; p += TA_THREADS) {
        const int hy = ty0 + (p / HA_W) - 1;
        const int hx = tx0 + (p % HA_W) - 1;
        if ((unsigned)hy < IMG && (unsigned)hx < IMG) {
            const char* src = (const char*)(ximg + ((size_t)hy * IMG + hx) * CH);
            #pragma unroll
            for (int q = 0; q < 4; q++)
                cp_async16(smem_base + (OFF_SX + q * SXQ + p * 4) * 4, src + q * 16);
        } else {
            const float4 z = make_float4(0.f, 0.f, 0.f, 0.f);
            #pragma unroll
            for (int q = 0; q < 4; q++)
                *(float4*)(sxp + q * SXQ + p * 4) = z;
        }
    }
    asm volatile("cp.async.commit_group;");
    asm volatile("cp.async.wait_group 0;");
    __syncthreads();

    // --- perceive: 1 thread = 1 pixel, all 16 channels -> 48 features ---
    {
        const int pty = tid >> 5, ptx = tid & 31;
        const int pcen = (pty + 1) * HA_W + (ptx + 1);

        float feat[48];
        #pragma unroll
        for (int q = 0; q < 4; q++) {
            const float* pl = sxp + q * SXQ;
            const float4 v00 = *(const float4*)(pl + (pcen - HA_W - 1) * 4);
            const float4 v01 = *(const float4*)(pl + (pcen - HA_W    ) * 4);
            const float4 v02 = *(const float4*)(pl + (pcen - HA_W + 1) * 4);
            const float4 v10 = *(const float4*)(pl + (pcen        - 1) * 4);
            const float4 v11 = *(const float4*)(pl + (pcen           ) * 4);
            const float4 v12 = *(const float4*)(pl + (pcen        + 1) * 4);
            const float4 v20 = *(const float4*)(pl + (pcen + HA_W - 1) * 4);
            const float4 v21 = *(const float4*)(pl + (pcen + HA_W    ) * 4);
            const float4 v22 = *(const float4*)(pl + (pcen + HA_W + 1) * 4);

            #define NCA_SOB(MEM, RI)                                                  \
            {                                                                         \
                const int fb = 12 * q + 3 * RI;                                       \
                feat[fb + 0] = v11.MEM;                                               \
                feat[fb + 1] = ((v02.MEM + v22.MEM) - (v00.MEM + v20.MEM)             \
                                + 2.0f * (v12.MEM - v10.MEM)) * 0.125f;               \
                feat[fb + 2] = ((v20.MEM + v22.MEM) - (v00.MEM + v02.MEM)             \
                                + 2.0f * (v21.MEM - v01.MEM)) * 0.125f;               \
            }
            NCA_SOB(x, 0) NCA_SOB(y, 1) NCA_SOB(z, 2) NCA_SOB(w, 3)
            #undef NCA_SOB
        }

        uint32_t* yrow = sY + tid * YSTRIDE;
        #pragma unroll
        for (int s = 0; s < 3; s++) {
            #pragma unroll
            for (int u = 0; u < 2; u++) {
                const int fb = 16 * s + 4 * u;
                uint4 wv;
                wv.x = pk2h(feat[fb + 0],  feat[fb + 1]);
                wv.y = pk2h(feat[fb + 8],  feat[fb + 9]);
                wv.z = pk2h(feat[fb + 2],  feat[fb + 3]);
                wv.w = pk2h(feat[fb + 10], feat[fb + 11]);
                *(uint4*)(yrow + 8 * s + 4 * u) = wv;
            }
        }
    }
    // Y rows consumed by this warp were written only by this warp's threads.
    __syncwarp();

    // --- prefetch rmask (4 pixels per thread: 2 tiles x 2 rows) ---
    const int gy = ty0 + warp;
    const size_t rowbase = ((size_t)b * IMG + gy) * IMG + tx0;
    float rmv[2][2];
    #pragma unroll
    for (int tt = 0; tt < 2; tt++)
        #pragma unroll
        for (int rr = 0; rr < 2; rr++)
            rmv[tt][rr] = rmask[rowbase + 16 * tt + gid + 8 * rr];

    // --- A-fragments for both m16 tiles ---
    uint32_t a1f[2][3][4];
    #pragma unroll
    for (int tt = 0; tt < 2; tt++) {
        const int rb = warp * 32 + 16 * tt;
        #pragma unroll
        for (int s = 0; s < 3; s++) {
            const uint2 lo = *(const uint2*)(sY + (rb + gid)     * YSTRIDE + 8 * s + 2 * tig);
            const uint2 hi = *(const uint2*)(sY + (rb + gid + 8) * YSTRIDE + 8 * s + 2 * tig);
            a1f[tt][s][0] = lo.x;  a1f[tt][s][1] = hi.x;
            a1f[tt][s][2] = lo.y;  a1f[tt][s][3] = hi.y;
        }
    }

    // --- fused GEMM1 -> relu/pack -> GEMM2, B-frags shared by both tiles ---
    float d[2][2][4];
    #pragma unroll
    for (int tt = 0; tt < 2; tt++)
        #pragma unroll
        for (int jj = 0; jj < 2; jj++)
            #pragma unroll
            for (int q = 0; q < 4; q++) d[tt][jj][q] = 0.0f;

    #pragma unroll
    for (int s2 = 0; s2 < 8; s2++) {
        float aA0[4] = {0.f,0.f,0.f,0.f}, aA1[4] = {0.f,0.f,0.f,0.f};
        float aB0[4] = {0.f,0.f,0.f,0.f}, aB1[4] = {0.f,0.f,0.f,0.f};
        #pragma unroll
        for (int s = 0; s < 3; s++) {
            const uint4 bb4 = ((const uint4*)w0f)[(s * 8 + s2) * 32 + lane];
            mma_f16(aA0, a1f[0][s][0], a1f[0][s][1], a1f[0][s][2], a1f[0][s][3], bb4.x, bb4.y);
            mma_f16(aA1, a1f[0][s][0], a1f[0][s][1], a1f[0][s][2], a1f[0][s][3], bb4.z, bb4.w);
            mma_f16(aB0, a1f[1][s][0], a1f[1][s][1], a1f[1][s][2], a1f[1][s][3], bb4.x, bb4.y);
            mma_f16(aB1, a1f[1][s][0], a1f[1][s][1], a1f[1][s][2], a1f[1][s][3], bb4.z, bb4.w);
        }
        const uint4 b2 = ((const uint4*)w1f)[s2 * 32 + lane];
        {
            const uint32_t f0 = pk2h(fmaxf(aA0[0], 0.f), fmaxf(aA0[1], 0.f));
            const uint32_t f1 = pk2h(fmaxf(aA0[2], 0.f), fmaxf(aA0[3], 0.f));
            const uint32_t f2 = pk2h(fmaxf(aA1[0], 0.f), fmaxf(aA1[1], 0.f));
            const uint32_t f3 = pk2h(fmaxf(aA1[2], 0.f), fmaxf(aA1[3], 0.f));
            mma_f16(d[0][0], f0, f1, f2, f3, b2.x, b2.y);
            mma_f16(d[0][1], f0, f1, f2, f3, b2.z, b2.w);
        }
        {
            const uint32_t f0 = pk2h(fmaxf(aB0[0], 0.f), fmaxf(aB0[1], 0.f));
            const uint32_t f1 = pk2h(fmaxf(aB0[2], 0.f), fmaxf(aB0[3], 0.f));
            const uint32_t f2 = pk2h(fmaxf(aB1[0], 0.f), fmaxf(aB1[1], 0.f));
            const uint32_t f3 = pk2h(fmaxf(aB1[2], 0.f), fmaxf(aB1[3], 0.f));
            mma_f16(d[1][0], f0, f1, f2, f3, b2.x, b2.y);
            mma_f16(d[1][1], f0, f1, f2, f3, b2.z, b2.w);
        }
    }

    // --- epilogue: x_new = x + dx*(rand<=0.5) -> OUT directly ---
    #pragma unroll
    for (int tt = 0; tt < 2; tt++) {
        #pragma unroll
        for (int rr = 0; rr < 2; rr++) {
            const int ptx = 16 * tt + gid + 8 * rr;
            const int pc = (warp + 1) * HA_W + (ptx + 1);
            const size_t pix = rowbase + ptx;
            const float upd = (rmv[tt][rr] <= 0.5f) ? 1.0f : 0.0f;
            #pragma unroll
            for (int jj = 0; jj < 2; jj++) {
                const int ch = 8 * jj + 2 * tig;
                const int q = ch >> 2, rm2 = ch & 3;
                const float2 xv = *(const float2*)(sxp + q * SXQ + pc * 4 + rm2);
                float2 v;
                v.x = xv.x + d[tt][jj][2 * rr + 0] * upd;
                v.y = xv.y + d[tt][jj][2 * rr + 1] * upd;
                *(float2*)(out + pix * CH + ch) = v;
                if (jj == 0 && tig == 1) {       // ch pair (2,3): alpha = .y
                    g_aon[pix] = make_float2(xv.y, v.y);   // (old, new)
                }
            }
        }
    }
}

// ------------------------------- Pass B (fix-up) ----------------------------
#define TB_H 8
#define TB_W 32
#define HB_H (TB_H + 2)
#define HB_W (TB_W + 2)
#define TB_THREADS (TB_H * TB_W)   // 256

__global__ __launch_bounds__(TB_THREADS)
void nca_pass_b(float* __restrict__ out)
{
    __shared__ float2 saon[HB_H * HB_W];

    const int tid = threadIdx.x;
    int bb = blockIdx.x;
    const int tx0 = (bb % (IMG / TB_W)) * TB_W;  bb /= (IMG / TB_W);
    const int ty0 = (bb % (IMG / TB_H)) * TB_H;  bb /= (IMG / TB_H);
    const int b = bb;
    const size_t ibase = (size_t)b * IMG * IMG;

    for (int p = tid; p < HB_H * HB_W; p += TB_THREADS) {
        const int hy = ty0 + (p / HB_W) - 1;
        const int hx = tx0 + (p % HB_W) - 1;
        saon[p] = ((unsigned)hy < IMG && (unsigned)hx < IMG)
                    ? g_aon[ibase + (size_t)hy * IMG + hx]
                    : make_float2(0.f, 0.f);
    }
    __syncthreads();

    const int ty = tid / TB_W, tx = tid % TB_W;
    const int pc = (ty + 1) * HB_W + (tx + 1);

    float mo, mn;
    {
        float2 m = saon[pc - HB_W - 1];
        #define NCA_MX(OFF) { float2 t = saon[pc + (OFF)]; \
                              m.x = fmaxf(m.x, t.x); m.y = fmaxf(m.y, t.y); }
        NCA_MX(-HB_W) NCA_MX(-HB_W + 1)
        NCA_MX(-1)    NCA_MX(0)    NCA_MX(1)
        NCA_MX(HB_W - 1) NCA_MX(HB_W) NCA_MX(HB_W + 1)
        #undef NCA_MX
        mo = m.x; mn = m.y;
    }

    if (!(mo > 0.1f && mn > 0.1f)) {
        const size_t pix = ibase + (size_t)(ty0 + ty) * IMG + (tx0 + tx);
        float4* dst = (float4*)(out + pix * CH);
        const float4 z = make_float4(0.f, 0.f, 0.f, 0.f);
        dst[0] = z; dst[1] = z; dst[2] = z; dst[3] = z;
    }
}

// ----------------------------------------------------------------------------
extern "C" void kernel_launch(void* const* d_in, const int* in_sizes, int n_in,
                              void* d_out, int out_size)
{
    (void)in_sizes; (void)n_in; (void)out_size;
    const float* x  = (const float*)d_in[0];
    const float* w0 = (const float*)d_in[1];
    const float* w1 = (const float*)d_in[2];
    const float* rm = (const float*)d_in[3];
    float* out = (float*)d_out;

    cudaFuncSetAttribute(nca_pass_a, cudaFuncAttributeMaxDynamicSharedMemorySize,
                         SMEM_A_BYTES);

    const int grid_a = BATCH * (IMG / TA_H) * (IMG / TA_W); // 4096
    const int grid_b = BATCH * (IMG / TB_H) * (IMG / TB_W); // 4096

    nca_pack<<<12, 128>>>(w0, w1);
    nca_pass_a<<<grid_a, TA_THREADS, SMEM_A_BYTES>>>(x, rm, out);
    nca_pass_b<<<grid_b, TB_THREADS>>>(out);
}

// round 10
// speedup vs baseline: 7.3664x; 1.0287x over previous
#include <cuda_runtime.h>
#include <cuda_fp16.h>
#include <math.h>
#include <stdint.h>

// ---------------------------------------------------------------------------
// Neural CA step, fp16 mma.sync (m16n8k16), fp32 accumulate.
//   Pass A: 8x32 px tile/block, 32 px/warp. Halo stored as half2 (2 planes,
//           conflict-free LDS.128 taps), stencil in half2, feature order
//           (id*16, sx*16, sy*16) with 0.125 folded into w0. Epilogue reads
//           exact fp32 x from gmem. x_new direct to out.
//   Pass B: fix-up — zero dead pixels; alpha planes packed as float2.
// ---------------------------------------------------------------------------

#define CH    16
#define NK    48
#define HID   128
#define IMG   256
#define BATCH 16

__device__ float2 g_aon[(size_t)BATCH * IMG * IMG];   // (alpha_old, alpha_new)
__device__ uint2 g_w0f[3 * 8 * 32 * 2];   // uint4-pairable GEMM1 B-frags
__device__ uint2 g_w1f[8 * 32 * 2];       // uint4-pairable GEMM2 B-frags

__device__ __forceinline__ uint32_t pk2h(float lo, float hi) {
    __half2 h = __floats2half2_rn(lo, hi);
    return *(uint32_t*)&h;
}
__device__ __forceinline__ uint32_t hadd2u(uint32_t a, uint32_t b) {
    uint32_t r; asm("add.f16x2 %0, %1, %2;" : "=r"(r) : "r"(a), "r"(b)); return r;
}
__device__ __forceinline__ uint32_t hsub2u(uint32_t a, uint32_t b) {
    uint32_t r; asm("sub.f16x2 %0, %1, %2;" : "=r"(r) : "r"(a), "r"(b)); return r;
}

__device__ __forceinline__ void mma_f16(float c[4],
                                        uint32_t a0, uint32_t a1, uint32_t a2, uint32_t a3,
                                        uint32_t b0, uint32_t b1) {
    asm volatile(
        "mma.sync.aligned.m16n8k16.row.col.f32.f16.f16.f32 "
        "{%0,%1,%2,%3}, {%4,%5,%6,%7}, {%8,%9}, {%0,%1,%2,%3};"
        : "+f"(c[0]), "+f"(c[1]), "+f"(c[2]), "+f"(c[3])
        : "r"(a0), "r"(a1), "r"(a2), "r"(a3), "r"(b0), "r"(b1));
}

__device__ __forceinline__ void cp_async16(uint32_t saddr, const void* gptr) {
    asm volatile("cp.async.cg.shared.global [%0], [%1], 16;"
                 :: "r"(saddr), "l"(gptr));
}

// ---------------------------- setup: pack weights ---------------------------
// Feature order k' : [0,16) = identity ch, [16,32) = sobel_x ch, [32,48) = sobel_y ch.
// Original w0 column for (type t, channel c) is 3c+t; sobel scale 0.125 folded in.
__device__ __forceinline__ float w0g(const float* w0, int n, int kp) {
    const int t = kp >> 4, c = kp & 15;
    const float v = w0[n * NK + 3 * c + t];
    return t ? v * 0.125f : v;
}

__global__ void nca_pack(const float* __restrict__ w0, const float* __restrict__ w1)
{
    const int idx = blockIdx.x * blockDim.x + threadIdx.x;
    if (idx < 3 * 8 * 32 * 2) {
        const int which = idx & 1;
        const int lane  = (idx >> 1) & 31;
        const int s2    = (idx >> 6) & 7;
        const int s     = idx >> 9;
        const int j = 2 * s2 + which;
        const int kp = 16 * s + 2 * (lane & 3);
        const int n = 8 * j + (lane >> 2);
        g_w0f[idx] = make_uint2(pk2h(w0g(w0, n, kp),     w0g(w0, n, kp + 1)),
                                pk2h(w0g(w0, n, kp + 8), w0g(w0, n, kp + 9)));
    }
    if (idx < 8 * 32 * 2) {
        const int jj   = idx & 1;
        const int lane = (idx >> 1) & 31;
        const int s    = idx >> 6;
        const int k = 16 * s + 2 * (lane & 3);
        const int n = 8 * jj + (lane >> 2);
        g_w1f[idx] = make_uint2(pk2h(w1[n * HID + k],     w1[n * HID + k + 1]),
                                pk2h(w1[n * HID + k + 8], w1[n * HID + k + 9]));
    }
}

// ------------------------------- Pass A ------------------------------------
#define TA_H 8
#define TA_W 32
#define HA_H (TA_H + 2)              // 10
#define HA_W (TA_W + 2)              // 34
#define TA_THREADS 256               // 8 warps, 32 pixels each (2 m16 tiles)
#define HA_PIX (HA_H * HA_W)         // 340
#define PLSTRIDE (HA_PIX * 4 + 4)    // 1364 u32 per half2 plane (8 ch each)
#define YSTRIDE 24                   // u32 words per Y row

// smem layout (32-bit words)
#define OFF_SXH  0                                   // 2 planes * 1364
#define OFF_SY   (OFF_SXH + 2 * PLSTRIDE)            // 2728
#define OFF_W0F  (OFF_SY + 256 * YSTRIDE)            // 8872
#define OFF_W1F  (OFF_W0F + 3072)                    // 11944
#define SMEM_A_WORDS (OFF_W1F + 1024)                // 12968
#define SMEM_A_BYTES (SMEM_A_WORDS * 4)              // 51872

__global__ __launch_bounds__(TA_THREADS, 3)
void nca_pass_a(const float* __restrict__ x,
                const float* __restrict__ rmask,
                float* __restrict__ out)
{
    extern __shared__ float smem[];
    uint32_t* sxh = (uint32_t*)smem + OFF_SXH;   // [2 planes][340 px][4 h2]
    uint32_t* sY  = (uint32_t*)smem + OFF_SY;
    uint32_t* w0f = (uint32_t*)smem + OFF_W0F;
    uint32_t* w1f = (uint32_t*)smem + OFF_W1F;

    const int tid  = threadIdx.x;
    const int lane = tid & 31;
    const int warp = tid >> 5;
    const int tig  = lane & 3;
    const int gid  = lane >> 2;

    const uint32_t smem_base = (uint32_t)__cvta_generic_to_shared(smem);

    // --- weight smem fill via cp.async (pre-packed, coalesced) ---
    {
        const uint32_t dst0 = smem_base + OFF_W0F * 4;
        #pragma unroll
        for (int i = 0; i < 3; i++)
            cp_async16(dst0 + (tid + 256 * i) * 16, (const char*)g_w0f + (tid + 256 * i) * 16);
        cp_async16(smem_base + OFF_W1F * 4 + tid * 16, (const char*)g_w1f + tid * 16);
        asm volatile("cp.async.commit_group;");
    }

    // --- block -> (b, ty0, tx0) ---
    int bb = blockIdx.x;
    const int tx0 = (bb & 7) * TA_W;   bb >>= 3;     // IMG/TA_W = 8
    const int ty0 = (bb & 31) * TA_H;  bb >>= 5;     // IMG/TA_H = 32
    const int b = bb;
    const float* ximg = x + (size_t)b * IMG * IMG * CH;

    // --- halo fill: LDG float4 x4 -> half2 -> 2 STS.128 (one per plane) ---
    for (int p = tid; p < HA_PIX; p += TA_THREADS) {
        const int hy = ty0 + (p / HA_W) - 1;
        const int hx = tx0 + (p % HA_W) - 1;
        uint4 pl0 = make_uint4(0u, 0u, 0u, 0u);
        uint4 pl1 = make_uint4(0u, 0u, 0u, 0u);
        if ((unsigned)hy < IMG && (unsigned)hx < IMG) {
            const float4* src = (const float4*)(ximg + ((size_t)hy * IMG + hx) * CH);
            const float4 v0 = src[0], v1 = src[1], v2 = src[2], v3 = src[3];
            pl0 = make_uint4(pk2h(v0.x, v0.y), pk2h(v0.z, v0.w),
                             pk2h(v1.x, v1.y), pk2h(v1.z, v1.w));
            pl1 = make_uint4(pk2h(v2.x, v2.y), pk2h(v2.z, v2.w),
                             pk2h(v3.x, v3.y), pk2h(v3.z, v3.w));
        }
        *(uint4*)(sxh + p * 4) = pl0;
        *(uint4*)(sxh + PLSTRIDE + p * 4) = pl1;
    }
    asm volatile("cp.async.wait_group 0;");
    __syncthreads();

    // --- perceive: 1 thread = 1 pixel; half2 stencil, 9 taps x 2 planes ---
    {
        const int pty = tid >> 5, ptx = tid & 31;
        const int pcen = (pty + 1) * HA_W + (ptx + 1);

        uint32_t feat[24];   // words: id[0..7], sx[8..15], sy[16..23]
        #pragma unroll
        for (int q = 0; q < 2; q++) {
            const uint32_t* pl = sxh + q * PLSTRIDE;
            const uint4 t0 = *(const uint4*)(pl + (pcen - HA_W - 1) * 4);
            const uint4 t1 = *(const uint4*)(pl + (pcen - HA_W    ) * 4);
            const uint4 t2 = *(const uint4*)(pl + (pcen - HA_W + 1) * 4);
            const uint4 t3 = *(const uint4*)(pl + (pcen        - 1) * 4);
            const uint4 t4 = *(const uint4*)(pl + (pcen           ) * 4);
            const uint4 t5 = *(const uint4*)(pl + (pcen        + 1) * 4);
            const uint4 t6 = *(const uint4*)(pl + (pcen + HA_W - 1) * 4);
            const uint4 t7 = *(const uint4*)(pl + (pcen + HA_W    ) * 4);
            const uint4 t8 = *(const uint4*)(pl + (pcen + HA_W + 1) * 4);

            #define NCA_STEN(W, WI)                                            \
            {                                                                  \
                const int wi = q * 4 + (WI);                                   \
                feat[wi] = t4.W;                                               \
                const uint32_t sa = hsub2u(hadd2u(t2.W, t8.W),                 \
                                           hadd2u(t0.W, t6.W));                \
                const uint32_t sd = hsub2u(t5.W, t3.W);                        \
                feat[8 + wi] = hadd2u(sa, hadd2u(sd, sd));                     \
                const uint32_t ya = hsub2u(hadd2u(t6.W, t8.W),                 \
                                           hadd2u(t0.W, t2.W));                \
                const uint32_t yd = hsub2u(t7.W, t1.W);                        \
                feat[16 + wi] = hadd2u(ya, hadd2u(yd, yd));                    \
            }
            NCA_STEN(x, 0) NCA_STEN(y, 1) NCA_STEN(z, 2) NCA_STEN(w, 3)
            #undef NCA_STEN
        }

        // Y store with physw permutation baked in: phys uint4 = (w0,w4,w1,w5),(w2,w6,w3,w7)
        uint32_t* yrow = sY + tid * YSTRIDE;
        #pragma unroll
        for (int g = 0; g < 3; g++) {
            *(uint4*)(yrow + 8 * g)     = make_uint4(feat[8*g + 0], feat[8*g + 4],
                                                     feat[8*g + 1], feat[8*g + 5]);
            *(uint4*)(yrow + 8 * g + 4) = make_uint4(feat[8*g + 2], feat[8*g + 6],
                                                     feat[8*g + 3], feat[8*g + 7]);
        }
    }
    // Y rows consumed by this warp were written only by this warp's threads.
    __syncwarp();

    // --- prefetch rmask (4 pixels per thread: 2 tiles x 2 rows) ---
    const int gy = ty0 + warp;
    const size_t rowbase = ((size_t)b * IMG + gy) * IMG + tx0;
    float rmv[2][2];
    #pragma unroll
    for (int tt = 0; tt < 2; tt++)
        #pragma unroll
        for (int rr = 0; rr < 2; rr++)
            rmv[tt][rr] = rmask[rowbase + 16 * tt + gid + 8 * rr];

    // --- A-fragments for both m16 tiles ---
    uint32_t a1f[2][3][4];
    #pragma unroll
    for (int tt = 0; tt < 2; tt++) {
        const int rb = warp * 32 + 16 * tt;
        #pragma unroll
        for (int s = 0; s < 3; s++) {
            const uint2 lo = *(const uint2*)(sY + (rb + gid)     * YSTRIDE + 8 * s + 2 * tig);
            const uint2 hi = *(const uint2*)(sY + (rb + gid + 8) * YSTRIDE + 8 * s + 2 * tig);
            a1f[tt][s][0] = lo.x;  a1f[tt][s][1] = hi.x;
            a1f[tt][s][2] = lo.y;  a1f[tt][s][3] = hi.y;
        }
    }

    // --- fused GEMM1 -> relu/pack -> GEMM2, B-frags shared by both tiles ---
    float d[2][2][4];
    #pragma unroll
    for (int tt = 0; tt < 2; tt++)
        #pragma unroll
        for (int jj = 0; jj < 2; jj++)
            #pragma unroll
            for (int q = 0; q < 4; q++) d[tt][jj][q] = 0.0f;

    #pragma unroll
    for (int s2 = 0; s2 < 8; s2++) {
        float aA0[4] = {0.f,0.f,0.f,0.f}, aA1[4] = {0.f,0.f,0.f,0.f};
        float aB0[4] = {0.f,0.f,0.f,0.f}, aB1[4] = {0.f,0.f,0.f,0.f};
        #pragma unroll
        for (int s = 0; s < 3; s++) {
            const uint4 bb4 = ((const uint4*)w0f)[(s * 8 + s2) * 32 + lane];
            mma_f16(aA0, a1f[0][s][0], a1f[0][s][1], a1f[0][s][2], a1f[0][s][3], bb4.x, bb4.y);
            mma_f16(aA1, a1f[0][s][0], a1f[0][s][1], a1f[0][s][2], a1f[0][s][3], bb4.z, bb4.w);
            mma_f16(aB0, a1f[1][s][0], a1f[1][s][1], a1f[1][s][2], a1f[1][s][3], bb4.x, bb4.y);
            mma_f16(aB1, a1f[1][s][0], a1f[1][s][1], a1f[1][s][2], a1f[1][s][3], bb4.z, bb4.w);
        }
        const uint4 b2 = ((const uint4*)w1f)[s2 * 32 + lane];
        {
            const uint32_t f0 = pk2h(fmaxf(aA0[0], 0.f), fmaxf(aA0[1], 0.f));
            const uint32_t f1 = pk2h(fmaxf(aA0[2], 0.f), fmaxf(aA0[3], 0.f));
            const uint32_t f2 = pk2h(fmaxf(aA1[0], 0.f), fmaxf(aA1[1], 0.f));
            const uint32_t f3 = pk2h(fmaxf(aA1[2], 0.f), fmaxf(aA1[3], 0.f));
            mma_f16(d[0][0], f0, f1, f2, f3, b2.x, b2.y);
            mma_f16(d[0][1], f0, f1, f2, f3, b2.z, b2.w);
        }
        {
            const uint32_t f0 = pk2h(fmaxf(aB0[0], 0.f), fmaxf(aB0[1], 0.f));
            const uint32_t f1 = pk2h(fmaxf(aB0[2], 0.f), fmaxf(aB0[3], 0.f));
            const uint32_t f2 = pk2h(fmaxf(aB1[0], 0.f), fmaxf(aB1[1], 0.f));
            const uint32_t f3 = pk2h(fmaxf(aB1[2], 0.f), fmaxf(aB1[3], 0.f));
            mma_f16(d[1][0], f0, f1, f2, f3, b2.x, b2.y);
            mma_f16(d[1][1], f0, f1, f2, f3, b2.z, b2.w);
        }
    }

    // --- epilogue: x_new = x(gmem, fp32 exact) + dx*(rand<=0.5) -> OUT ---
    #pragma unroll
    for (int tt = 0; tt < 2; tt++) {
        #pragma unroll
        for (int rr = 0; rr < 2; rr++) {
            const int ptx = 16 * tt + gid + 8 * rr;
            const size_t pix = rowbase + ptx;
            const float upd = (rmv[tt][rr] <= 0.5f) ? 1.0f : 0.0f;
            #pragma unroll
            for (int jj = 0; jj < 2; jj++) {
                const int ch = 8 * jj + 2 * tig;
                const float2 xv = *(const float2*)(x + pix * CH + ch);
                float2 v;
                v.x = xv.x + d[tt][jj][2 * rr + 0] * upd;
                v.y = xv.y + d[tt][jj][2 * rr + 1] * upd;
                *(float2*)(out + pix * CH + ch) = v;
                if (jj == 0 && tig == 1) {       // ch pair (2,3): alpha = .y
                    g_aon[pix] = make_float2(xv.y, v.y);   // (old, new)
                }
            }
        }
    }
}

// ------------------------------- Pass B (fix-up) ----------------------------
#define TB_H 8
#define TB_W 32
#define HB_H (TB_H + 2)
#define HB_W (TB_W + 2)
#define TB_THREADS (TB_H * TB_W)   // 256

__global__ __launch_bounds__(TB_THREADS)
void nca_pass_b(float* __restrict__ out)
{
    __shared__ float2 saon[HB_H * HB_W];

    const int tid = threadIdx.x;
    int bb = blockIdx.x;
    const int tx0 = (bb % (IMG / TB_W)) * TB_W;  bb /= (IMG / TB_W);
    const int ty0 = (bb % (IMG / TB_H)) * TB_H;  bb /= (IMG / TB_H);
    const int b = bb;
    const size_t ibase = (size_t)b * IMG * IMG;

    for (int p = tid; p < HB_H * HB_W; p += TB_THREADS) {
        const int hy = ty0 + (p / HB_W) - 1;
        const int hx = tx0 + (p % HB_W) - 1;
        saon[p] = ((unsigned)hy < IMG && (unsigned)hx < IMG)
                    ? g_aon[ibase + (size_t)hy * IMG + hx]
                    : make_float2(0.f, 0.f);
    }
    __syncthreads();

    const int ty = tid / TB_W, tx = tid % TB_W;
    const int pc = (ty + 1) * HB_W + (tx + 1);

    float mo, mn;
    {
        float2 m = saon[pc - HB_W - 1];
        #define NCA_MX(OFF) { float2 t = saon[pc + (OFF)]; \
                              m.x = fmaxf(m.x, t.x); m.y = fmaxf(m.y, t.y); }
        NCA_MX(-HB_W) NCA_MX(-HB_W + 1)
        NCA_MX(-1)    NCA_MX(0)    NCA_MX(1)
        NCA_MX(HB_W - 1) NCA_MX(HB_W) NCA_MX(HB_W + 1)
        #undef NCA_MX
        mo = m.x; mn = m.y;
    }

    if (!(mo > 0.1f && mn > 0.1f)) {
        const size_t pix = ibase + (size_t)(ty0 + ty) * IMG + (tx0 + tx);
        float4* dst = (float4*)(out + pix * CH);
        const float4 z = make_float4(0.f, 0.f, 0.f, 0.f);
        dst[0] = z; dst[1] = z; dst[2] = z; dst[3] = z;
    }
}

// ----------------------------------------------------------------------------
extern "C" void kernel_launch(void* const* d_in, const int* in_sizes, int n_in,
                              void* d_out, int out_size)
{
    (void)in_sizes; (void)n_in; (void)out_size;
    const float* x  = (const float*)d_in[0];
    const float* w0 = (const float*)d_in[1];
    const float* w1 = (const float*)d_in[2];
    const float* rm = (const float*)d_in[3];
    float* out = (float*)d_out;

    cudaFuncSetAttribute(nca_pass_a, cudaFuncAttributeMaxDynamicSharedMemorySize,
                         SMEM_A_BYTES);

    const int grid_a = BATCH * (IMG / TA_H) * (IMG / TA_W); // 4096
    const int grid_b = BATCH * (IMG / TB_H) * (IMG / TB_W); // 4096

    nca_pack<<<12, 128>>>(w0, w1);
    nca_pass_a<<<grid_a, TA_THREADS, SMEM_A_BYTES>>>(x, rm, out);
    nca_pass_b<<<grid_b, TB_THREADS>>>(out);
}